// round 1
// baseline (speedup 1.0000x reference)
#include <cuda_runtime.h>
#include <math.h>

#define NB 2
#define NT 2048
#define ND 1024
#define NH 16
#define NDH 64
#define NDI 4096
#define NM (NB*NT)          // 4096 rows
#define EPS_ 1e-5f

// ---------------- scratch (no cudaMalloc allowed) ----------------
__device__ float g_Zn  [(size_t)NM * ND];
__device__ float g_QKV [(size_t)NM * 3 * ND];
__device__ float g_attn[(size_t)NM * ND];
__device__ float g_Z1  [(size_t)NM * ND];
__device__ float g_Zn2 [(size_t)NM * ND];
__device__ float g_h   [(size_t)NM * NDI];

// ---------------- LayerNorm: one block per row, 256 threads ----------------
__global__ void ln_kernel(const float* __restrict__ X,
                          const float* __restrict__ g,
                          const float* __restrict__ b,
                          float* __restrict__ Y) {
    int row = blockIdx.x;
    int t = threadIdx.x;                       // 256 threads * float4 = 1024
    float4 v = reinterpret_cast<const float4*>(X + (size_t)row * ND)[t];
    float s  = v.x + v.y + v.z + v.w;
    float sq = v.x*v.x + v.y*v.y + v.z*v.z + v.w*v.w;
    #pragma unroll
    for (int o = 16; o > 0; o >>= 1) {
        s  += __shfl_xor_sync(0xffffffffu, s,  o);
        sq += __shfl_xor_sync(0xffffffffu, sq, o);
    }
    __shared__ float ss[8], ssq[8];
    int w = t >> 5, l = t & 31;
    if (l == 0) { ss[w] = s; ssq[w] = sq; }
    __syncthreads();
    if (w == 0) {
        s = ss[l & 7]; sq = ssq[l & 7];
        #pragma unroll
        for (int o = 4; o > 0; o >>= 1) {
            s  += __shfl_xor_sync(0xffffffffu, s,  o);
            sq += __shfl_xor_sync(0xffffffffu, sq, o);
        }
        if (l == 0) { ss[0] = s; ssq[0] = sq; }
    }
    __syncthreads();
    s = ss[0]; sq = ssq[0];
    float mu  = s * (1.0f / ND);
    float var = sq * (1.0f / ND) - mu * mu;
    float rstd = rsqrtf(var + EPS_);
    float4 gv = reinterpret_cast<const float4*>(g)[t];
    float4 bv = reinterpret_cast<const float4*>(b)[t];
    float4 y;
    y.x = (v.x - mu) * rstd * gv.x + bv.x;
    y.y = (v.y - mu) * rstd * gv.y + bv.y;
    y.z = (v.z - mu) * rstd * gv.z + bv.z;
    y.w = (v.w - mu) * rstd * gv.w + bv.w;
    reinterpret_cast<float4*>(Y + (size_t)row * ND)[t] = y;
}

// ---------------- generic C = A @ W^T (+bias)(+act)(+resid) ----------------
// A: [M,K] row-major, W: [N,K] row-major. 128x128x8 tile, 256 thr, 8x8 micro.
__global__ __launch_bounds__(256, 2) void gemm_nt(
    const float* __restrict__ A, const float* __restrict__ W,
    const float* __restrict__ bias, const float* __restrict__ resid,
    float* __restrict__ C, int M, int N, int K, int act) {
    __shared__ float As[8][128];
    __shared__ float Ws[8][128];
    const int tid = threadIdx.x;
    const int ty = tid >> 4, tx = tid & 15;
    const int srow = tid >> 1;
    const int k4 = (tid & 1) * 4;
    const float* Aptr = A + (size_t)(blockIdx.y * 128 + srow) * K + k4;
    const float* Wptr = W + (size_t)(blockIdx.x * 128 + srow) * K + k4;

    float acc[8][8];
    #pragma unroll
    for (int i = 0; i < 8; i++)
        #pragma unroll
        for (int j = 0; j < 8; j++) acc[i][j] = 0.f;

    for (int kt = 0; kt < K; kt += 8) {
        float4 a = *reinterpret_cast<const float4*>(Aptr + kt);
        float4 w = *reinterpret_cast<const float4*>(Wptr + kt);
        As[k4+0][srow] = a.x; As[k4+1][srow] = a.y;
        As[k4+2][srow] = a.z; As[k4+3][srow] = a.w;
        Ws[k4+0][srow] = w.x; Ws[k4+1][srow] = w.y;
        Ws[k4+2][srow] = w.z; Ws[k4+3][srow] = w.w;
        __syncthreads();
        #pragma unroll
        for (int k = 0; k < 8; k++) {
            float ra[8], rb[8];
            *reinterpret_cast<float4*>(ra)     = *reinterpret_cast<const float4*>(&As[k][ty*8]);
            *reinterpret_cast<float4*>(ra + 4) = *reinterpret_cast<const float4*>(&As[k][ty*8+4]);
            *reinterpret_cast<float4*>(rb)     = *reinterpret_cast<const float4*>(&Ws[k][tx*8]);
            *reinterpret_cast<float4*>(rb + 4) = *reinterpret_cast<const float4*>(&Ws[k][tx*8+4]);
            #pragma unroll
            for (int i = 0; i < 8; i++)
                #pragma unroll
                for (int j = 0; j < 8; j++)
                    acc[i][j] = fmaf(ra[i], rb[j], acc[i][j]);
        }
        __syncthreads();
    }

    const int crow = blockIdx.y * 128 + ty * 8;
    const int ccol = blockIdx.x * 128 + tx * 8;
    float bv[8];
    if (bias) {
        *reinterpret_cast<float4*>(bv)     = *reinterpret_cast<const float4*>(bias + ccol);
        *reinterpret_cast<float4*>(bv + 4) = *reinterpret_cast<const float4*>(bias + ccol + 4);
    } else {
        #pragma unroll
        for (int j = 0; j < 8; j++) bv[j] = 0.f;
    }
    #pragma unroll
    for (int i = 0; i < 8; i++) {
        size_t base = (size_t)(crow + i) * N + ccol;
        float v[8];
        #pragma unroll
        for (int j = 0; j < 8; j++) {
            float t = acc[i][j] + bv[j];
            if (act == 1) t = fmaxf(t, 0.f);
            v[j] = t;
        }
        if (resid) {
            float4 r0 = *reinterpret_cast<const float4*>(resid + base);
            float4 r1 = *reinterpret_cast<const float4*>(resid + base + 4);
            v[0]+=r0.x; v[1]+=r0.y; v[2]+=r0.z; v[3]+=r0.w;
            v[4]+=r1.x; v[5]+=r1.y; v[6]+=r1.z; v[7]+=r1.w;
        }
        *reinterpret_cast<float4*>(C + base)     = *reinterpret_cast<float4*>(v);
        *reinterpret_cast<float4*>(C + base + 4) = *reinterpret_cast<float4*>(v + 4);
    }
}

// ---------------- fused attention ----------------
// QKV layout per token row (3072): per head h, [V(64) | Q(64) | K(64)].
// Grid: (NT/64, NH, NB); 128 threads: ty=tid/16 owns 8 q-rows, tx=tid%16 owns 4 cols.
// Online softmax with unmasked denominator; numerator uses exp * mask * V.
// Output written with leaky_relu applied (feeds O-proj directly).
__global__ __launch_bounds__(128) void attn_kernel(
    const float* __restrict__ QKV,
    const float* __restrict__ nmask,
    const float* __restrict__ mask,
    float* __restrict__ O) {
    __shared__ float Qs[64][64];    // transposed: Qs[d][r]
    __shared__ float KPs[64][64];   // K transposed [d][c]; reused as P [r][c]
    __shared__ float Vs[64][64];    // natural: Vs[k][d]

    const int tid = threadIdx.x;
    const int ty = tid >> 4;
    const int tx = tid & 15;
    const int b  = blockIdx.z;
    const int h  = blockIdx.y;
    const int q0 = blockIdx.x * 64;

    const size_t rs = 3 * ND;
    const float* Vb = QKV + (size_t)b * NT * rs + h * 192;
    const float* Qb = Vb + 64;
    const float* Kb = Vb + 128;

    // load Q tile transposed
    #pragma unroll
    for (int it = 0; it < 8; it++) {
        int s = tid + it * 128;
        int r = s >> 4;
        int d4 = (s & 15) << 2;
        float4 v = *reinterpret_cast<const float4*>(Qb + (size_t)(q0 + r) * rs + d4);
        Qs[d4+0][r] = v.x; Qs[d4+1][r] = v.y; Qs[d4+2][r] = v.z; Qs[d4+3][r] = v.w;
    }

    float acc[8][4], mrow[8], lrow[8];
    #pragma unroll
    for (int i = 0; i < 8; i++) {
        mrow[i] = -1e30f; lrow[i] = 0.f;
        acc[i][0]=acc[i][1]=acc[i][2]=acc[i][3]=0.f;
    }
    const size_t mbase = (size_t)b * NT * NT;

    for (int kt = 0; kt < NT; kt += 64) {
        __syncthreads();   // prev AV done (and Q tile visible on first iter)
        #pragma unroll
        for (int it = 0; it < 8; it++) {
            int s = tid + it * 128;
            int r = s >> 4;
            int d4 = (s & 15) << 2;
            float4 kv = *reinterpret_cast<const float4*>(Kb + (size_t)(kt + r) * rs + d4);
            KPs[d4+0][r] = kv.x; KPs[d4+1][r] = kv.y; KPs[d4+2][r] = kv.z; KPs[d4+3][r] = kv.w;
            float4 vv = *reinterpret_cast<const float4*>(Vb + (size_t)(kt + r) * rs + d4);
            *reinterpret_cast<float4*>(&Vs[r][d4]) = vv;
        }
        __syncthreads();

        // S = Q K^T
        float sc[8][4];
        #pragma unroll
        for (int i = 0; i < 8; i++) sc[i][0]=sc[i][1]=sc[i][2]=sc[i][3]=0.f;
        #pragma unroll 4
        for (int d = 0; d < 64; d++) {
            float qa[8], kb4[4];
            *reinterpret_cast<float4*>(qa)     = *reinterpret_cast<const float4*>(&Qs[d][ty*8]);
            *reinterpret_cast<float4*>(qa + 4) = *reinterpret_cast<const float4*>(&Qs[d][ty*8+4]);
            *reinterpret_cast<float4*>(kb4)    = *reinterpret_cast<const float4*>(&KPs[d][tx*4]);
            #pragma unroll
            for (int i = 0; i < 8; i++)
                #pragma unroll
                for (int j = 0; j < 4; j++)
                    sc[i][j] = fmaf(qa[i], kb4[j], sc[i][j]);
        }

        // scale + new_mask + online softmax stats (row groups of 16 lanes)
        float corr[8];
        #pragma unroll
        for (int i = 0; i < 8; i++) {
            size_t moff = mbase + (size_t)(q0 + ty*8 + i) * NT + kt + tx*4;
            float4 nm = *reinterpret_cast<const float4*>(nmask + moff);
            sc[i][0] = fmaf(sc[i][0], 0.125f, nm.x);
            sc[i][1] = fmaf(sc[i][1], 0.125f, nm.y);
            sc[i][2] = fmaf(sc[i][2], 0.125f, nm.z);
            sc[i][3] = fmaf(sc[i][3], 0.125f, nm.w);
            float tmax = fmaxf(fmaxf(sc[i][0], sc[i][1]), fmaxf(sc[i][2], sc[i][3]));
            #pragma unroll
            for (int o = 8; o > 0; o >>= 1)
                tmax = fmaxf(tmax, __shfl_xor_sync(0xffffffffu, tmax, o));
            float nmx = fmaxf(mrow[i], tmax);
            float c = __expf(mrow[i] - nmx);
            mrow[i] = nmx;
            sc[i][0] = __expf(sc[i][0] - nmx);
            sc[i][1] = __expf(sc[i][1] - nmx);
            sc[i][2] = __expf(sc[i][2] - nmx);
            sc[i][3] = __expf(sc[i][3] - nmx);
            float tsum = sc[i][0] + sc[i][1] + sc[i][2] + sc[i][3];
            #pragma unroll
            for (int o = 8; o > 0; o >>= 1)
                tsum += __shfl_xor_sync(0xffffffffu, tsum, o);
            lrow[i] = lrow[i] * c + tsum;
            corr[i] = c;
        }

        __syncthreads();   // all K reads done before P overwrites the buffer

        // P = exp * mask into smem; rescale accumulators
        #pragma unroll
        for (int i = 0; i < 8; i++) {
            size_t moff = mbase + (size_t)(q0 + ty*8 + i) * NT + kt + tx*4;
            float4 mk = *reinterpret_cast<const float4*>(mask + moff);
            float4 pv;
            pv.x = sc[i][0] * mk.x; pv.y = sc[i][1] * mk.y;
            pv.z = sc[i][2] * mk.z; pv.w = sc[i][3] * mk.w;
            *reinterpret_cast<float4*>(&KPs[ty*8+i][tx*4]) = pv;
            acc[i][0]*=corr[i]; acc[i][1]*=corr[i]; acc[i][2]*=corr[i]; acc[i][3]*=corr[i];
        }
        __syncthreads();

        // O += P @ V
        #pragma unroll 2
        for (int kk = 0; kk < 64; kk += 4) {
            float4 pr[8];
            #pragma unroll
            for (int i = 0; i < 8; i++)
                pr[i] = *reinterpret_cast<const float4*>(&KPs[ty*8+i][kk]);
            float4 v0 = *reinterpret_cast<const float4*>(&Vs[kk+0][tx*4]);
            float4 v1 = *reinterpret_cast<const float4*>(&Vs[kk+1][tx*4]);
            float4 v2 = *reinterpret_cast<const float4*>(&Vs[kk+2][tx*4]);
            float4 v3 = *reinterpret_cast<const float4*>(&Vs[kk+3][tx*4]);
            #pragma unroll
            for (int i = 0; i < 8; i++) {
                acc[i][0]=fmaf(pr[i].x,v0.x,acc[i][0]); acc[i][1]=fmaf(pr[i].x,v0.y,acc[i][1]);
                acc[i][2]=fmaf(pr[i].x,v0.z,acc[i][2]); acc[i][3]=fmaf(pr[i].x,v0.w,acc[i][3]);
                acc[i][0]=fmaf(pr[i].y,v1.x,acc[i][0]); acc[i][1]=fmaf(pr[i].y,v1.y,acc[i][1]);
                acc[i][2]=fmaf(pr[i].y,v1.z,acc[i][2]); acc[i][3]=fmaf(pr[i].y,v1.w,acc[i][3]);
                acc[i][0]=fmaf(pr[i].z,v2.x,acc[i][0]); acc[i][1]=fmaf(pr[i].z,v2.y,acc[i][1]);
                acc[i][2]=fmaf(pr[i].z,v2.z,acc[i][2]); acc[i][3]=fmaf(pr[i].z,v2.w,acc[i][3]);
                acc[i][0]=fmaf(pr[i].w,v3.x,acc[i][0]); acc[i][1]=fmaf(pr[i].w,v3.y,acc[i][1]);
                acc[i][2]=fmaf(pr[i].w,v3.z,acc[i][2]); acc[i][3]=fmaf(pr[i].w,v3.w,acc[i][3]);
            }
        }
    }

    // normalize, leaky_relu, store [b,n,h,d]
    #pragma unroll
    for (int i = 0; i < 8; i++) {
        float inv = 1.0f / lrow[i];
        float4 o;
        o.x = acc[i][0]*inv; o.y = acc[i][1]*inv;
        o.z = acc[i][2]*inv; o.w = acc[i][3]*inv;
        o.x = o.x >= 0.f ? o.x : 0.01f*o.x;
        o.y = o.y >= 0.f ? o.y : 0.01f*o.y;
        o.z = o.z >= 0.f ? o.z : 0.01f*o.z;
        o.w = o.w >= 0.f ? o.w : 0.01f*o.w;
        *reinterpret_cast<float4*>(O + (size_t)(b*NT + q0 + ty*8 + i) * ND + h*64 + tx*4) = o;
    }
}

// ---------------- launch ----------------
extern "C" void kernel_launch(void* const* d_in, const int* in_sizes, int n_in,
                              void* d_out, int out_size) {
    const float* Z     = (const float*)d_in[0];
    const float* nmask = (const float*)d_in[1];
    const float* mask  = (const float*)d_in[2];
    const float* ln1g  = (const float*)d_in[3];
    const float* ln1b  = (const float*)d_in[4];
    const float* qkvw  = (const float*)d_in[5];
    const float* qkvb  = (const float*)d_in[6];
    const float* ow    = (const float*)d_in[7];
    const float* ln2g  = (const float*)d_in[8];
    const float* ln2b  = (const float*)d_in[9];
    const float* p1w   = (const float*)d_in[10];
    const float* p1b   = (const float*)d_in[11];
    const float* p2w   = (const float*)d_in[12];
    const float* p2b   = (const float*)d_in[13];
    float* out = (float*)d_out;

    float *Zn, *QKV, *attn, *Z1, *Zn2, *hbuf;
    cudaGetSymbolAddress((void**)&Zn,   g_Zn);
    cudaGetSymbolAddress((void**)&QKV,  g_QKV);
    cudaGetSymbolAddress((void**)&attn, g_attn);
    cudaGetSymbolAddress((void**)&Z1,   g_Z1);
    cudaGetSymbolAddress((void**)&Zn2,  g_Zn2);
    cudaGetSymbolAddress((void**)&hbuf, g_h);

    ln_kernel<<<NM, 256>>>(Z, ln1g, ln1b, Zn);
    gemm_nt<<<dim3(3*ND/128, NM/128), 256>>>(Zn, qkvw, qkvb, nullptr, QKV, NM, 3*ND, ND, 0);
    attn_kernel<<<dim3(NT/64, NH, NB), 128>>>(QKV, nmask, mask, attn);
    gemm_nt<<<dim3(ND/128, NM/128), 256>>>(attn, ow, nullptr, Z, Z1, NM, ND, ND, 0);
    ln_kernel<<<NM, 256>>>(Z1, ln2g, ln2b, Zn2);
    gemm_nt<<<dim3(NDI/128, NM/128), 256>>>(Zn2, p1w, p1b, nullptr, hbuf, NM, NDI, ND, 1);
    gemm_nt<<<dim3(ND/128, NM/128), 256>>>(hbuf, p2w, p2b, Z1, out, NM, ND, NDI, 0);
}

// round 4
// speedup vs baseline: 1.9428x; 1.9428x over previous
#include <cuda_runtime.h>
#include <cuda_bf16.h>
#include <math.h>
#include <cstdint>

#define NB 2
#define NT 2048
#define ND 1024
#define NH 16
#define NDI 4096
#define NM (NB*NT)          // 4096 rows
#define EPS_ 1e-5f

// ---------------- scratch (no cudaMalloc allowed) ----------------
__device__ __nv_bfloat16 g_Znh [(size_t)NM * ND];
__device__ __nv_bfloat16 g_Znl [(size_t)NM * ND];
__device__ float         g_QKV [(size_t)NM * 3 * ND];
__device__ __nv_bfloat16 g_ah  [(size_t)NM * ND];
__device__ __nv_bfloat16 g_al  [(size_t)NM * ND];
__device__ float         g_Z1  [(size_t)NM * ND];
__device__ __nv_bfloat16 g_Zn2h[(size_t)NM * ND];
__device__ __nv_bfloat16 g_Zn2l[(size_t)NM * ND];
__device__ __nv_bfloat16 g_hh  [(size_t)NM * NDI];
__device__ __nv_bfloat16 g_hl  [(size_t)NM * NDI];
__device__ __nv_bfloat16 g_wqh [(size_t)3*ND*ND];
__device__ __nv_bfloat16 g_wql [(size_t)3*ND*ND];
__device__ __nv_bfloat16 g_woh [(size_t)ND*ND];
__device__ __nv_bfloat16 g_wol [(size_t)ND*ND];
__device__ __nv_bfloat16 g_w1h [(size_t)NDI*ND];
__device__ __nv_bfloat16 g_w1l [(size_t)NDI*ND];
__device__ __nv_bfloat16 g_w2h [(size_t)ND*NDI];
__device__ __nv_bfloat16 g_w2l [(size_t)ND*NDI];

// ---------------- helpers ----------------
__device__ __forceinline__ uint32_t smem_u32(const void* p) {
    uint32_t a;
    asm("{ .reg .u64 t; cvta.to.shared.u64 t, %1; cvt.u32.u64 %0, t; }" : "=r"(a) : "l"(p));
    return a;
}

#define LDM4(r, addr) \
    asm volatile("ldmatrix.sync.aligned.m8n8.x4.shared.b16 {%0,%1,%2,%3}, [%4];" \
        : "=r"((r)[0]), "=r"((r)[1]), "=r"((r)[2]), "=r"((r)[3]) : "r"(addr))

__device__ __forceinline__ void mma16816(float* c, const uint32_t* a,
                                         uint32_t b0, uint32_t b1) {
    asm volatile("mma.sync.aligned.m16n8k16.row.col.f32.bf16.bf16.f32 "
        "{%0,%1,%2,%3}, {%4,%5,%6,%7}, {%8,%9}, {%0,%1,%2,%3};"
        : "+f"(c[0]), "+f"(c[1]), "+f"(c[2]), "+f"(c[3])
        : "r"(a[0]), "r"(a[1]), "r"(a[2]), "r"(a[3]), "r"(b0), "r"(b1));
}

#define CP_ASYNC16(dst, src) \
    asm volatile("cp.async.cg.shared.global [%0], [%1], 16;" :: "r"(dst), "l"(src) : "memory")
#define CP_COMMIT() asm volatile("cp.async.commit_group;" ::: "memory")
#define CP_WAIT1()  asm volatile("cp.async.wait_group 1;" ::: "memory")
#define CP_WAIT0()  asm volatile("cp.async.wait_group 0;" ::: "memory")

__device__ __forceinline__ void split2(float x, __nv_bfloat16& h, __nv_bfloat16& l) {
    h = __float2bfloat16(x);
    l = __float2bfloat16(x - __bfloat162float(h));
}

// ---------------- weight split: fp32 -> (hi, lo) bf16 ----------------
__global__ void split_kernel(const float* __restrict__ X,
                             __nv_bfloat16* __restrict__ H,
                             __nv_bfloat16* __restrict__ L, int n4) {
    int i = blockIdx.x * blockDim.x + threadIdx.x;
    if (i >= n4) return;
    float4 v = reinterpret_cast<const float4*>(X)[i];
    __nv_bfloat16 h0, h1, h2, h3, l0, l1, l2, l3;
    split2(v.x, h0, l0); split2(v.y, h1, l1); split2(v.z, h2, l2); split2(v.w, h3, l3);
    reinterpret_cast<__nv_bfloat162*>(H)[2*i]   = __nv_bfloat162(h0, h1);
    reinterpret_cast<__nv_bfloat162*>(H)[2*i+1] = __nv_bfloat162(h2, h3);
    reinterpret_cast<__nv_bfloat162*>(L)[2*i]   = __nv_bfloat162(l0, l1);
    reinterpret_cast<__nv_bfloat162*>(L)[2*i+1] = __nv_bfloat162(l2, l3);
}

// ---------------- LayerNorm -> (hi, lo) bf16 ----------------
__global__ void ln_kernel(const float* __restrict__ X,
                          const float* __restrict__ g,
                          const float* __restrict__ b,
                          __nv_bfloat16* __restrict__ Yh,
                          __nv_bfloat16* __restrict__ Yl) {
    int row = blockIdx.x;
    int t = threadIdx.x;
    float4 v = reinterpret_cast<const float4*>(X + (size_t)row * ND)[t];
    float s  = v.x + v.y + v.z + v.w;
    float sq = v.x*v.x + v.y*v.y + v.z*v.z + v.w*v.w;
    #pragma unroll
    for (int o = 16; o > 0; o >>= 1) {
        s  += __shfl_xor_sync(0xffffffffu, s,  o);
        sq += __shfl_xor_sync(0xffffffffu, sq, o);
    }
    __shared__ float ss[8], ssq[8];
    int w = t >> 5, l = t & 31;
    if (l == 0) { ss[w] = s; ssq[w] = sq; }
    __syncthreads();
    if (w == 0) {
        s = ss[l & 7]; sq = ssq[l & 7];
        #pragma unroll
        for (int o = 4; o > 0; o >>= 1) {
            s  += __shfl_xor_sync(0xffffffffu, s,  o);
            sq += __shfl_xor_sync(0xffffffffu, sq, o);
        }
        if (l == 0) { ss[0] = s; ssq[0] = sq; }
    }
    __syncthreads();
    s = ss[0]; sq = ssq[0];
    float mu  = s * (1.0f / ND);
    float var = sq * (1.0f / ND) - mu * mu;
    float rstd = rsqrtf(var + EPS_);
    float4 gv = reinterpret_cast<const float4*>(g)[t];
    float4 bv = reinterpret_cast<const float4*>(b)[t];
    float y0 = (v.x - mu) * rstd * gv.x + bv.x;
    float y1 = (v.y - mu) * rstd * gv.y + bv.y;
    float y2 = (v.z - mu) * rstd * gv.z + bv.z;
    float y3 = (v.w - mu) * rstd * gv.w + bv.w;
    __nv_bfloat16 h0,h1,h2,h3,l0,l1,l2,l3;
    split2(y0,h0,l0); split2(y1,h1,l1); split2(y2,h2,l2); split2(y3,h3,l3);
    size_t base = (size_t)row * ND + t * 4;
    reinterpret_cast<__nv_bfloat162*>(Yh + base)[0] = __nv_bfloat162(h0, h1);
    reinterpret_cast<__nv_bfloat162*>(Yh + base)[1] = __nv_bfloat162(h2, h3);
    reinterpret_cast<__nv_bfloat162*>(Yl + base)[0] = __nv_bfloat162(l0, l1);
    reinterpret_cast<__nv_bfloat162*>(Yl + base)[1] = __nv_bfloat162(l2, l3);
}

// ---------------- HMMA bf16x3 GEMM:  C = A @ W^T ----------------
// A = Ah+Al [M,K], W = Bh+Bl [N,K], fp32 accumulate (regs).
// CTA 128x128, 8 warps (2m x 4n), warp tile 64x32, K chunk 64 (SW128 rows),
// cp.async double-buffered. mode 0: outf = acc(+bias)(+resid); mode 1: relu->(h,l).
#define GT_BUF 65536u
__global__ __launch_bounds__(256, 1) void gemm_tc(
    const __nv_bfloat16* __restrict__ Ah, const __nv_bfloat16* __restrict__ Al,
    const __nv_bfloat16* __restrict__ Bh, const __nv_bfloat16* __restrict__ Bl,
    const float* __restrict__ bias, const float* __restrict__ resid,
    float* __restrict__ outf, __nv_bfloat16* __restrict__ outh,
    __nv_bfloat16* __restrict__ outl,
    int M, int N, int K, int mode) {
    extern __shared__ char dsm[];

    const int tid  = threadIdx.x;
    const int wid  = tid >> 5;
    const int lane = tid & 31;
    const int m0 = blockIdx.y * 128;
    const int n0 = blockIdx.x * 128;
    const int wm = wid >> 2;          // 0..1
    const int wn = wid & 3;           // 0..3

    // 1024-align dynamic smem
    uint32_t u0 = smem_u32(dsm);
    uint32_t pad = (1024u - (u0 & 1023u)) & 1023u;
    char* sp = dsm + pad;
    uint32_t smem_al = u0 + pad;

    // ---- loader: tile t (0=Ah 1=Al 2=Bh 3=Bl), 64 threads/tile ----
    const int t  = tid >> 6;
    const int lt = tid & 63;
    const int r0 = lt >> 3;          // starting row (step 8)
    const int cu = lt & 7;           // 16B unit within 128B row
    const __nv_bfloat16* srcs[4] = {
        Ah + (size_t)m0 * K, Al + (size_t)m0 * K,
        Bh + (size_t)n0 * K, Bl + (size_t)n0 * K };
    const char* tsrc = (const char*)srcs[t] + (size_t)r0 * K * 2 + cu * 16;
    const size_t rstride8 = (size_t)8 * K * 2;
    const uint32_t toff = (uint32_t)t * 16384u;

    auto load_chunk = [&](int c, int b) {
        const char* src = tsrc + (size_t)c * 128;
        uint32_t dstb = smem_al + (uint32_t)b * GT_BUF + toff;
        #pragma unroll
        for (int i = 0; i < 16; i++) {
            uint32_t byte = (uint32_t)(r0 + 8 * i) * 128u + (uint32_t)cu * 16u;
            uint32_t sw = byte ^ ((byte >> 3) & 0x70u);
            CP_ASYNC16(dstb + sw, src + (size_t)i * rstride8);
        }
    };

    // ---- ldmatrix per-lane addressing ----
    const int sel = lane >> 3;        // matrix index 0..3
    const int rin = lane & 7;
    // A x4: mat0 (m0-7,k0-7), mat1 (m8-15,k0-7), mat2 (m0-7,k8-15), mat3 (m8-15,k8-15)
    const int aRowOff = ((sel & 1) << 3) + rin;
    const uint32_t aKB = (uint32_t)(sel >> 1) * 16u;
    // B x4: mat0 (n0-7,k0-7), mat1 (n0-7,k8-15), mat2 (n8-15,k0-7), mat3 (n8-15,k8-15)
    const int bRowOff = ((sel >> 1) << 3) + rin;
    const uint32_t bKB = (uint32_t)(sel & 1) * 16u;
    const uint32_t xorv = (uint32_t)rin << 4;

    uint32_t aBase[4], bBase[2];
    #pragma unroll
    for (int mt = 0; mt < 4; mt++)
        aBase[mt] = (uint32_t)(wm * 64 + mt * 16 + aRowOff) * 128u;
    #pragma unroll
    for (int bt = 0; bt < 2; bt++)
        bBase[bt] = (uint32_t)(wn * 32 + bt * 16 + bRowOff) * 128u;

    float acc[4][4][4];
    #pragma unroll
    for (int i = 0; i < 4; i++)
        #pragma unroll
        for (int j = 0; j < 4; j++)
            acc[i][j][0]=acc[i][j][1]=acc[i][j][2]=acc[i][j][3]=0.f;

    const int nc = K >> 6;
    load_chunk(0, 0);
    CP_COMMIT();

    for (int c = 0; c < nc; ++c) {
        if (c + 1 < nc) { load_chunk(c + 1, (c + 1) & 1); CP_COMMIT(); CP_WAIT1(); }
        else            { CP_WAIT0(); }
        __syncthreads();

        const uint32_t bb = smem_al + (uint32_t)(c & 1) * GT_BUF;
        #pragma unroll
        for (int ks = 0; ks < 4; ks++) {
            uint32_t ahr[4][4], alr[4][4], bhr[2][4], blr[2][4];
            const uint32_t ka = ((uint32_t)ks * 32u + aKB) ^ xorv;
            const uint32_t kb = ((uint32_t)ks * 32u + bKB) ^ xorv;
            #pragma unroll
            for (int mt = 0; mt < 4; mt++) {
                uint32_t ad = bb + aBase[mt] + ka;
                LDM4(ahr[mt], ad);
                LDM4(alr[mt], ad + 16384u);
            }
            #pragma unroll
            for (int bt = 0; bt < 2; bt++) {
                uint32_t bd = bb + 32768u + bBase[bt] + kb;
                LDM4(bhr[bt], bd);
                LDM4(blr[bt], bd + 16384u);
            }
            #pragma unroll
            for (int mt = 0; mt < 4; mt++)
                #pragma unroll
                for (int nt = 0; nt < 4; nt++) {
                    const int bt = nt >> 1, p = (nt & 1) * 2;
                    mma16816(acc[mt][nt], ahr[mt], bhr[bt][p], bhr[bt][p+1]);
                    mma16816(acc[mt][nt], ahr[mt], blr[bt][p], blr[bt][p+1]);
                    mma16816(acc[mt][nt], alr[mt], bhr[bt][p], bhr[bt][p+1]);
                }
        }
        __syncthreads();
    }

    // ---- epilogue: regs -> smem (stride 129) -> coalesced gmem ----
    {
        float* ep = (float*)sp;
        const int g = lane >> 2, tg = lane & 3;
        #pragma unroll
        for (int mt = 0; mt < 4; mt++)
            #pragma unroll
            for (int nt = 0; nt < 4; nt++) {
                int rr = wm * 64 + mt * 16 + g;
                int cc = wn * 32 + nt * 8 + tg * 2;
                ep[rr * 129 + cc]       = acc[mt][nt][0];
                ep[rr * 129 + cc + 1]   = acc[mt][nt][1];
                ep[(rr+8) * 129 + cc]   = acc[mt][nt][2];
                ep[(rr+8) * 129 + cc+1] = acc[mt][nt][3];
            }
    }
    __syncthreads();
    {
        float* ep = (float*)sp;
        for (int j = tid; j < 4096; j += 256) {
            int r = j >> 5;
            int c4 = (j & 31) << 2;
            int col = n0 + c4;
            size_t gbase = (size_t)(m0 + r) * N + col;
            float v[4];
            #pragma unroll
            for (int k = 0; k < 4; k++) {
                v[k] = ep[r * 129 + c4 + k];
                if (bias) v[k] += bias[col + k];
            }
            if (mode == 1) {
                __nv_bfloat16 h[4], l[4];
                #pragma unroll
                for (int k = 0; k < 4; k++) {
                    v[k] = fmaxf(v[k], 0.f);
                    split2(v[k], h[k], l[k]);
                }
                reinterpret_cast<__nv_bfloat162*>(outh + gbase)[0] = __nv_bfloat162(h[0], h[1]);
                reinterpret_cast<__nv_bfloat162*>(outh + gbase)[1] = __nv_bfloat162(h[2], h[3]);
                reinterpret_cast<__nv_bfloat162*>(outl + gbase)[0] = __nv_bfloat162(l[0], l[1]);
                reinterpret_cast<__nv_bfloat162*>(outl + gbase)[1] = __nv_bfloat162(l[2], l[3]);
            } else {
                if (resid) {
                    float4 rr = *reinterpret_cast<const float4*>(resid + gbase);
                    v[0] += rr.x; v[1] += rr.y; v[2] += rr.z; v[3] += rr.w;
                }
                float4 o; o.x=v[0]; o.y=v[1]; o.z=v[2]; o.w=v[3];
                *reinterpret_cast<float4*>(outf + gbase) = o;
            }
        }
    }
}

// ---------------- fused attention (fp32 SIMT, bf16-pair output) ----------------
__global__ __launch_bounds__(128) void attn_kernel(
    const float* __restrict__ QKV,
    const float* __restrict__ nmask,
    const float* __restrict__ mask,
    __nv_bfloat16* __restrict__ Oh,
    __nv_bfloat16* __restrict__ Ol) {
    __shared__ float Qs[64][64];
    __shared__ float KPs[64][64];
    __shared__ float Vs[64][64];

    const int tid = threadIdx.x;
    const int ty = tid >> 4;
    const int tx = tid & 15;
    const int b  = blockIdx.z;
    const int h  = blockIdx.y;
    const int q0 = blockIdx.x * 64;

    const size_t rs = 3 * ND;
    const float* Vb = QKV + (size_t)b * NT * rs + h * 192;
    const float* Qb = Vb + 64;
    const float* Kb = Vb + 128;

    #pragma unroll
    for (int it = 0; it < 8; it++) {
        int s = tid + it * 128;
        int r = s >> 4;
        int d4 = (s & 15) << 2;
        float4 v = *reinterpret_cast<const float4*>(Qb + (size_t)(q0 + r) * rs + d4);
        Qs[d4+0][r] = v.x; Qs[d4+1][r] = v.y; Qs[d4+2][r] = v.z; Qs[d4+3][r] = v.w;
    }

    float acc[8][4], mrow[8], lrow[8];
    #pragma unroll
    for (int i = 0; i < 8; i++) {
        mrow[i] = -1e30f; lrow[i] = 0.f;
        acc[i][0]=acc[i][1]=acc[i][2]=acc[i][3]=0.f;
    }
    const size_t mbase = (size_t)b * NT * NT;

    for (int kt = 0; kt < NT; kt += 64) {
        __syncthreads();
        #pragma unroll
        for (int it = 0; it < 8; it++) {
            int s = tid + it * 128;
            int r = s >> 4;
            int d4 = (s & 15) << 2;
            float4 kv = *reinterpret_cast<const float4*>(Kb + (size_t)(kt + r) * rs + d4);
            KPs[d4+0][r] = kv.x; KPs[d4+1][r] = kv.y; KPs[d4+2][r] = kv.z; KPs[d4+3][r] = kv.w;
            float4 vv = *reinterpret_cast<const float4*>(Vb + (size_t)(kt + r) * rs + d4);
            *reinterpret_cast<float4*>(&Vs[r][d4]) = vv;
        }
        __syncthreads();

        float sc[8][4];
        #pragma unroll
        for (int i = 0; i < 8; i++) sc[i][0]=sc[i][1]=sc[i][2]=sc[i][3]=0.f;
        #pragma unroll 4
        for (int d = 0; d < 64; d++) {
            float qa[8], kb4[4];
            *reinterpret_cast<float4*>(qa)     = *reinterpret_cast<const float4*>(&Qs[d][ty*8]);
            *reinterpret_cast<float4*>(qa + 4) = *reinterpret_cast<const float4*>(&Qs[d][ty*8+4]);
            *reinterpret_cast<float4*>(kb4)    = *reinterpret_cast<const float4*>(&KPs[d][tx*4]);
            #pragma unroll
            for (int i = 0; i < 8; i++)
                #pragma unroll
                for (int j = 0; j < 4; j++)
                    sc[i][j] = fmaf(qa[i], kb4[j], sc[i][j]);
        }

        float corr[8];
        #pragma unroll
        for (int i = 0; i < 8; i++) {
            size_t moff = mbase + (size_t)(q0 + ty*8 + i) * NT + kt + tx*4;
            float4 nm = *reinterpret_cast<const float4*>(nmask + moff);
            sc[i][0] = fmaf(sc[i][0], 0.125f, nm.x);
            sc[i][1] = fmaf(sc[i][1], 0.125f, nm.y);
            sc[i][2] = fmaf(sc[i][2], 0.125f, nm.z);
            sc[i][3] = fmaf(sc[i][3], 0.125f, nm.w);
            float tmax = fmaxf(fmaxf(sc[i][0], sc[i][1]), fmaxf(sc[i][2], sc[i][3]));
            #pragma unroll
            for (int o = 8; o > 0; o >>= 1)
                tmax = fmaxf(tmax, __shfl_xor_sync(0xffffffffu, tmax, o));
            float nmx = fmaxf(mrow[i], tmax);
            float c = __expf(mrow[i] - nmx);
            mrow[i] = nmx;
            sc[i][0] = __expf(sc[i][0] - nmx);
            sc[i][1] = __expf(sc[i][1] - nmx);
            sc[i][2] = __expf(sc[i][2] - nmx);
            sc[i][3] = __expf(sc[i][3] - nmx);
            float tsum = sc[i][0] + sc[i][1] + sc[i][2] + sc[i][3];
            #pragma unroll
            for (int o = 8; o > 0; o >>= 1)
                tsum += __shfl_xor_sync(0xffffffffu, tsum, o);
            lrow[i] = lrow[i] * c + tsum;
            corr[i] = c;
        }

        __syncthreads();

        #pragma unroll
        for (int i = 0; i < 8; i++) {
            size_t moff = mbase + (size_t)(q0 + ty*8 + i) * NT + kt + tx*4;
            float4 mk = *reinterpret_cast<const float4*>(mask + moff);
            float4 pv;
            pv.x = sc[i][0] * mk.x; pv.y = sc[i][1] * mk.y;
            pv.z = sc[i][2] * mk.z; pv.w = sc[i][3] * mk.w;
            *reinterpret_cast<float4*>(&KPs[ty*8+i][tx*4]) = pv;
            acc[i][0]*=corr[i]; acc[i][1]*=corr[i]; acc[i][2]*=corr[i]; acc[i][3]*=corr[i];
        }
        __syncthreads();

        #pragma unroll 2
        for (int kk = 0; kk < 64; kk += 4) {
            float4 pr[8];
            #pragma unroll
            for (int i = 0; i < 8; i++)
                pr[i] = *reinterpret_cast<const float4*>(&KPs[ty*8+i][kk]);
            float4 v0 = *reinterpret_cast<const float4*>(&Vs[kk+0][tx*4]);
            float4 v1 = *reinterpret_cast<const float4*>(&Vs[kk+1][tx*4]);
            float4 v2 = *reinterpret_cast<const float4*>(&Vs[kk+2][tx*4]);
            float4 v3 = *reinterpret_cast<const float4*>(&Vs[kk+3][tx*4]);
            #pragma unroll
            for (int i = 0; i < 8; i++) {
                acc[i][0]=fmaf(pr[i].x,v0.x,acc[i][0]); acc[i][1]=fmaf(pr[i].x,v0.y,acc[i][1]);
                acc[i][2]=fmaf(pr[i].x,v0.z,acc[i][2]); acc[i][3]=fmaf(pr[i].x,v0.w,acc[i][3]);
                acc[i][0]=fmaf(pr[i].y,v1.x,acc[i][0]); acc[i][1]=fmaf(pr[i].y,v1.y,acc[i][1]);
                acc[i][2]=fmaf(pr[i].y,v1.z,acc[i][2]); acc[i][3]=fmaf(pr[i].y,v1.w,acc[i][3]);
                acc[i][0]=fmaf(pr[i].z,v2.x,acc[i][0]); acc[i][1]=fmaf(pr[i].z,v2.y,acc[i][1]);
                acc[i][2]=fmaf(pr[i].z,v2.z,acc[i][2]); acc[i][3]=fmaf(pr[i].z,v2.w,acc[i][3]);
                acc[i][0]=fmaf(pr[i].w,v3.x,acc[i][0]); acc[i][1]=fmaf(pr[i].w,v3.y,acc[i][1]);
                acc[i][2]=fmaf(pr[i].w,v3.z,acc[i][2]); acc[i][3]=fmaf(pr[i].w,v3.w,acc[i][3]);
            }
        }
    }

    #pragma unroll
    for (int i = 0; i < 8; i++) {
        float inv = 1.0f / lrow[i];
        float o[4];
        o[0] = acc[i][0]*inv; o[1] = acc[i][1]*inv;
        o[2] = acc[i][2]*inv; o[3] = acc[i][3]*inv;
        __nv_bfloat16 hh[4], ll[4];
        #pragma unroll
        for (int k = 0; k < 4; k++) {
            o[k] = o[k] >= 0.f ? o[k] : 0.01f * o[k];
            split2(o[k], hh[k], ll[k]);
        }
        size_t base = (size_t)(b*NT + q0 + ty*8 + i) * ND + h*64 + tx*4;
        reinterpret_cast<__nv_bfloat162*>(Oh + base)[0] = __nv_bfloat162(hh[0], hh[1]);
        reinterpret_cast<__nv_bfloat162*>(Oh + base)[1] = __nv_bfloat162(hh[2], hh[3]);
        reinterpret_cast<__nv_bfloat162*>(Ol + base)[0] = __nv_bfloat162(ll[0], ll[1]);
        reinterpret_cast<__nv_bfloat162*>(Ol + base)[1] = __nv_bfloat162(ll[2], ll[3]);
    }
}

// ---------------- launch ----------------
#define GT_SMEM (132096)

extern "C" void kernel_launch(void* const* d_in, const int* in_sizes, int n_in,
                              void* d_out, int out_size) {
    const float* Z     = (const float*)d_in[0];
    const float* nmask = (const float*)d_in[1];
    const float* mask  = (const float*)d_in[2];
    const float* ln1g  = (const float*)d_in[3];
    const float* ln1b  = (const float*)d_in[4];
    const float* qkvw  = (const float*)d_in[5];
    const float* qkvb  = (const float*)d_in[6];
    const float* ow    = (const float*)d_in[7];
    const float* ln2g  = (const float*)d_in[8];
    const float* ln2b  = (const float*)d_in[9];
    const float* p1w   = (const float*)d_in[10];
    const float* p1b   = (const float*)d_in[11];
    const float* p2w   = (const float*)d_in[12];
    const float* p2b   = (const float*)d_in[13];
    float* out = (float*)d_out;

    __nv_bfloat16 *Znh,*Znl,*ah,*al,*Zn2h,*Zn2l,*hh,*hl;
    __nv_bfloat16 *wqh,*wql,*woh,*wol,*w1h,*w1l,*w2h,*w2l;
    float *QKV, *Z1;
    cudaGetSymbolAddress((void**)&Znh,  g_Znh);  cudaGetSymbolAddress((void**)&Znl,  g_Znl);
    cudaGetSymbolAddress((void**)&QKV,  g_QKV);
    cudaGetSymbolAddress((void**)&ah,   g_ah);   cudaGetSymbolAddress((void**)&al,   g_al);
    cudaGetSymbolAddress((void**)&Z1,   g_Z1);
    cudaGetSymbolAddress((void**)&Zn2h, g_Zn2h); cudaGetSymbolAddress((void**)&Zn2l, g_Zn2l);
    cudaGetSymbolAddress((void**)&hh,   g_hh);   cudaGetSymbolAddress((void**)&hl,   g_hl);
    cudaGetSymbolAddress((void**)&wqh,  g_wqh);  cudaGetSymbolAddress((void**)&wql,  g_wql);
    cudaGetSymbolAddress((void**)&woh,  g_woh);  cudaGetSymbolAddress((void**)&wol,  g_wol);
    cudaGetSymbolAddress((void**)&w1h,  g_w1h);  cudaGetSymbolAddress((void**)&w1l,  g_w1l);
    cudaGetSymbolAddress((void**)&w2h,  g_w2h);  cudaGetSymbolAddress((void**)&w2l,  g_w2l);

    cudaFuncSetAttribute(gemm_tc, cudaFuncAttributeMaxDynamicSharedMemorySize, GT_SMEM);

    // weight splits
    split_kernel<<<(3*ND*ND/4 + 255)/256, 256>>>(qkvw, wqh, wql, 3*ND*ND/4);
    split_kernel<<<(ND*ND/4 + 255)/256, 256>>>(ow, woh, wol, ND*ND/4);
    split_kernel<<<(NDI*ND/4 + 255)/256, 256>>>(p1w, w1h, w1l, NDI*ND/4);
    split_kernel<<<(ND*NDI/4 + 255)/256, 256>>>(p2w, w2h, w2l, ND*NDI/4);

    ln_kernel<<<NM, 256>>>(Z, ln1g, ln1b, Znh, Znl);
    gemm_tc<<<dim3(3*ND/128, NM/128), 256, GT_SMEM>>>(
        Znh, Znl, wqh, wql, qkvb, nullptr, QKV, nullptr, nullptr, NM, 3*ND, ND, 0);
    attn_kernel<<<dim3(NT/64, NH, NB), 128>>>(QKV, nmask, mask, ah, al);
    gemm_tc<<<dim3(ND/128, NM/128), 256, GT_SMEM>>>(
        ah, al, woh, wol, nullptr, Z, Z1, nullptr, nullptr, NM, ND, ND, 0);
    ln_kernel<<<NM, 256>>>(Z1, ln2g, ln2b, Zn2h, Zn2l);
    gemm_tc<<<dim3(NDI/128, NM/128), 256, GT_SMEM>>>(
        Zn2h, Zn2l, w1h, w1l, p1b, nullptr, nullptr, hh, hl, NM, NDI, ND, 1);
    gemm_tc<<<dim3(ND/128, NM/128), 256, GT_SMEM>>>(
        hh, hl, w2h, w2l, p2b, Z1, out, nullptr, nullptr, NM, ND, NDI, 0);
}

// round 7
// speedup vs baseline: 2.7536x; 1.4173x over previous
#include <cuda_runtime.h>
#include <cuda_bf16.h>
#include <math.h>
#include <cstdint>

#define NB 2
#define NT 2048
#define ND 1024
#define NH 16
#define NDI 4096
#define NM (NB*NT)          // 4096 rows
#define EPS_ 1e-5f

// ---------------- scratch (no cudaMalloc allowed) ----------------
__device__ __nv_bfloat16 g_Znh [(size_t)NM * ND];
__device__ __nv_bfloat16 g_Znl [(size_t)NM * ND];
__device__ __nv_bfloat16 g_qkvh[(size_t)NM * 3 * ND];
__device__ __nv_bfloat16 g_qkvl[(size_t)NM * 3 * ND];
__device__ __nv_bfloat16 g_ah  [(size_t)NM * ND];
__device__ __nv_bfloat16 g_al  [(size_t)NM * ND];
__device__ float         g_Z1  [(size_t)NM * ND];
__device__ __nv_bfloat16 g_Zn2h[(size_t)NM * ND];
__device__ __nv_bfloat16 g_Zn2l[(size_t)NM * ND];
__device__ __nv_bfloat16 g_hh  [(size_t)NM * NDI];
__device__ __nv_bfloat16 g_hl  [(size_t)NM * NDI];
__device__ __nv_bfloat16 g_wqh [(size_t)3*ND*ND];
__device__ __nv_bfloat16 g_wql [(size_t)3*ND*ND];
__device__ __nv_bfloat16 g_woh [(size_t)ND*ND];
__device__ __nv_bfloat16 g_wol [(size_t)ND*ND];
__device__ __nv_bfloat16 g_w1h [(size_t)NDI*ND];
__device__ __nv_bfloat16 g_w1l [(size_t)NDI*ND];
__device__ __nv_bfloat16 g_w2h [(size_t)ND*NDI];
__device__ __nv_bfloat16 g_w2l [(size_t)ND*NDI];

// ---------------- helpers ----------------
__device__ __forceinline__ uint32_t smem_u32(const void* p) {
    uint32_t a;
    asm("{ .reg .u64 t; cvta.to.shared.u64 t, %1; cvt.u32.u64 %0, t; }" : "=r"(a) : "l"(p));
    return a;
}

__device__ __forceinline__ uint32_t pack_bf2(__nv_bfloat16 lo, __nv_bfloat16 hi) {
    return (uint32_t)__bfloat16_as_ushort(lo) | ((uint32_t)__bfloat16_as_ushort(hi) << 16);
}

#define LDM4(r, addr) \
    asm volatile("ldmatrix.sync.aligned.m8n8.x4.shared.b16 {%0,%1,%2,%3}, [%4];" \
        : "=r"((r)[0]), "=r"((r)[1]), "=r"((r)[2]), "=r"((r)[3]) : "r"(addr))
#define LDM4T(r, addr) \
    asm volatile("ldmatrix.sync.aligned.m8n8.x4.trans.shared.b16 {%0,%1,%2,%3}, [%4];" \
        : "=r"((r)[0]), "=r"((r)[1]), "=r"((r)[2]), "=r"((r)[3]) : "r"(addr))

__device__ __forceinline__ void mma16816(float* c, const uint32_t* a,
                                         uint32_t b0, uint32_t b1) {
    asm volatile("mma.sync.aligned.m16n8k16.row.col.f32.bf16.bf16.f32 "
        "{%0,%1,%2,%3}, {%4,%5,%6,%7}, {%8,%9}, {%0,%1,%2,%3};"
        : "+f"(c[0]), "+f"(c[1]), "+f"(c[2]), "+f"(c[3])
        : "r"(a[0]), "r"(a[1]), "r"(a[2]), "r"(a[3]), "r"(b0), "r"(b1));
}

#define CP_ASYNC16(dst, src) \
    asm volatile("cp.async.cg.shared.global [%0], [%1], 16;" :: "r"(dst), "l"(src) : "memory")
#define CP_COMMIT() asm volatile("cp.async.commit_group;" ::: "memory")
#define CP_WAIT1()  asm volatile("cp.async.wait_group 1;" ::: "memory")
#define CP_WAIT0()  asm volatile("cp.async.wait_group 0;" ::: "memory")

__device__ __forceinline__ void split2(float x, __nv_bfloat16& h, __nv_bfloat16& l) {
    h = __float2bfloat16(x);
    l = __float2bfloat16(x - __bfloat162float(h));
}

// fast exp via FMA (no MUFU): rel err ~2e-8
__device__ __forceinline__ float fexp(float x) {
    x = fmaxf(x, -87.0f);
    float t = fmaf(x, 1.4426950408889634f, 12582912.0f);
    int   i = __float_as_int(t) - 0x4B400000;
    float fi = t - 12582912.0f;
    float f  = fmaf(x, 1.4426950408889634f, -fi);
    float p  = 1.3333558146e-3f;
    p = fmaf(p, f, 9.6181291076e-3f);
    p = fmaf(p, f, 5.5504108664e-2f);
    p = fmaf(p, f, 2.4022650695910071e-1f);
    p = fmaf(p, f, 6.9314718055994531e-1f);
    p = fmaf(p, f, 1.0f);
    return __int_as_float(__float_as_int(p) + (i << 23));
}

// ---------------- weight split: fp32 -> (hi, lo) bf16 ----------------
__global__ void split_kernel(const float* __restrict__ X,
                             __nv_bfloat16* __restrict__ H,
                             __nv_bfloat16* __restrict__ L, int n4) {
    int i = blockIdx.x * blockDim.x + threadIdx.x;
    if (i >= n4) return;
    float4 v = reinterpret_cast<const float4*>(X)[i];
    __nv_bfloat16 h0, h1, h2, h3, l0, l1, l2, l3;
    split2(v.x, h0, l0); split2(v.y, h1, l1); split2(v.z, h2, l2); split2(v.w, h3, l3);
    reinterpret_cast<__nv_bfloat162*>(H)[2*i]   = __nv_bfloat162(h0, h1);
    reinterpret_cast<__nv_bfloat162*>(H)[2*i+1] = __nv_bfloat162(h2, h3);
    reinterpret_cast<__nv_bfloat162*>(L)[2*i]   = __nv_bfloat162(l0, l1);
    reinterpret_cast<__nv_bfloat162*>(L)[2*i+1] = __nv_bfloat162(l2, l3);
}

// ---------------- LayerNorm -> (hi, lo) bf16 ----------------
__global__ void ln_kernel(const float* __restrict__ X,
                          const float* __restrict__ g,
                          const float* __restrict__ b,
                          __nv_bfloat16* __restrict__ Yh,
                          __nv_bfloat16* __restrict__ Yl) {
    int row = blockIdx.x;
    int t = threadIdx.x;
    float4 v = reinterpret_cast<const float4*>(X + (size_t)row * ND)[t];
    float s  = v.x + v.y + v.z + v.w;
    float sq = v.x*v.x + v.y*v.y + v.z*v.z + v.w*v.w;
    #pragma unroll
    for (int o = 16; o > 0; o >>= 1) {
        s  += __shfl_xor_sync(0xffffffffu, s,  o);
        sq += __shfl_xor_sync(0xffffffffu, sq, o);
    }
    __shared__ float ss[8], ssq[8];
    int w = t >> 5, l = t & 31;
    if (l == 0) { ss[w] = s; ssq[w] = sq; }
    __syncthreads();
    if (w == 0) {
        s = ss[l & 7]; sq = ssq[l & 7];
        #pragma unroll
        for (int o = 4; o > 0; o >>= 1) {
            s  += __shfl_xor_sync(0xffffffffu, s,  o);
            sq += __shfl_xor_sync(0xffffffffu, sq, o);
        }
        if (l == 0) { ss[0] = s; ssq[0] = sq; }
    }
    __syncthreads();
    s = ss[0]; sq = ssq[0];
    float mu  = s * (1.0f / ND);
    float var = sq * (1.0f / ND) - mu * mu;
    float rstd = rsqrtf(var + EPS_);
    float4 gv = reinterpret_cast<const float4*>(g)[t];
    float4 bv = reinterpret_cast<const float4*>(b)[t];
    float y0 = (v.x - mu) * rstd * gv.x + bv.x;
    float y1 = (v.y - mu) * rstd * gv.y + bv.y;
    float y2 = (v.z - mu) * rstd * gv.z + bv.z;
    float y3 = (v.w - mu) * rstd * gv.w + bv.w;
    __nv_bfloat16 h0,h1,h2,h3,l0,l1,l2,l3;
    split2(y0,h0,l0); split2(y1,h1,l1); split2(y2,h2,l2); split2(y3,h3,l3);
    size_t base = (size_t)row * ND + t * 4;
    reinterpret_cast<__nv_bfloat162*>(Yh + base)[0] = __nv_bfloat162(h0, h1);
    reinterpret_cast<__nv_bfloat162*>(Yh + base)[1] = __nv_bfloat162(h2, h3);
    reinterpret_cast<__nv_bfloat162*>(Yl + base)[0] = __nv_bfloat162(l0, l1);
    reinterpret_cast<__nv_bfloat162*>(Yl + base)[1] = __nv_bfloat162(l2, l3);
}

// ---------------- HMMA bf16x3 GEMM:  C = A @ W^T ----------------
// mode 0: outf = acc(+bias)(+resid); mode 1: relu(acc+bias)->(h,l); mode 2: (acc+bias)->(h,l)
#define GT_BUF 65536u
__global__ __launch_bounds__(256, 1) void gemm_tc(
    const __nv_bfloat16* __restrict__ Ah, const __nv_bfloat16* __restrict__ Al,
    const __nv_bfloat16* __restrict__ Bh, const __nv_bfloat16* __restrict__ Bl,
    const float* __restrict__ bias, const float* __restrict__ resid,
    float* __restrict__ outf, __nv_bfloat16* __restrict__ outh,
    __nv_bfloat16* __restrict__ outl,
    int M, int N, int K, int mode) {
    extern __shared__ char dsm[];

    const int tid  = threadIdx.x;
    const int wid  = tid >> 5;
    const int lane = tid & 31;
    const int m0 = blockIdx.y * 128;
    const int n0 = blockIdx.x * 128;
    const int wm = wid >> 2;
    const int wn = wid & 3;

    uint32_t u0 = smem_u32(dsm);
    uint32_t pad = (1024u - (u0 & 1023u)) & 1023u;
    char* sp = dsm + pad;
    uint32_t smem_al = u0 + pad;

    const int t  = tid >> 6;
    const int lt = tid & 63;
    const int r0 = lt >> 3;
    const int cu = lt & 7;
    const __nv_bfloat16* srcs[4] = {
        Ah + (size_t)m0 * K, Al + (size_t)m0 * K,
        Bh + (size_t)n0 * K, Bl + (size_t)n0 * K };
    const char* tsrc = (const char*)srcs[t] + (size_t)r0 * K * 2 + cu * 16;
    const size_t rstride8 = (size_t)8 * K * 2;
    const uint32_t toff = (uint32_t)t * 16384u;

    auto load_chunk = [&](int c, int b) {
        const char* src = tsrc + (size_t)c * 128;
        uint32_t dstb = smem_al + (uint32_t)b * GT_BUF + toff;
        #pragma unroll
        for (int i = 0; i < 16; i++) {
            uint32_t byte = (uint32_t)(r0 + 8 * i) * 128u + (uint32_t)cu * 16u;
            uint32_t sw = byte ^ ((byte >> 3) & 0x70u);
            CP_ASYNC16(dstb + sw, src + (size_t)i * rstride8);
        }
    };

    const int sel = lane >> 3;
    const int rin = lane & 7;
    const int aRowOff = ((sel & 1) << 3) + rin;
    const uint32_t aKB = (uint32_t)(sel >> 1) * 16u;
    const int bRowOff = ((sel >> 1) << 3) + rin;
    const uint32_t bKB = (uint32_t)(sel & 1) * 16u;
    const uint32_t xorv = (uint32_t)rin << 4;

    uint32_t aBase[4], bBase[2];
    #pragma unroll
    for (int mt = 0; mt < 4; mt++)
        aBase[mt] = (uint32_t)(wm * 64 + mt * 16 + aRowOff) * 128u;
    #pragma unroll
    for (int bt = 0; bt < 2; bt++)
        bBase[bt] = (uint32_t)(wn * 32 + bt * 16 + bRowOff) * 128u;

    float acc[4][4][4];
    #pragma unroll
    for (int i = 0; i < 4; i++)
        #pragma unroll
        for (int j = 0; j < 4; j++)
            acc[i][j][0]=acc[i][j][1]=acc[i][j][2]=acc[i][j][3]=0.f;

    const int nc = K >> 6;
    load_chunk(0, 0);
    CP_COMMIT();

    for (int c = 0; c < nc; ++c) {
        if (c + 1 < nc) { load_chunk(c + 1, (c + 1) & 1); CP_COMMIT(); CP_WAIT1(); }
        else            { CP_WAIT0(); }
        __syncthreads();

        const uint32_t bb = smem_al + (uint32_t)(c & 1) * GT_BUF;
        #pragma unroll
        for (int ks = 0; ks < 4; ks++) {
            uint32_t ahr[4][4], alr[4][4], bhr[2][4], blr[2][4];
            const uint32_t ka = ((uint32_t)ks * 32u + aKB) ^ xorv;
            const uint32_t kb = ((uint32_t)ks * 32u + bKB) ^ xorv;
            #pragma unroll
            for (int mt = 0; mt < 4; mt++) {
                uint32_t ad = bb + aBase[mt] + ka;
                LDM4(ahr[mt], ad);
                LDM4(alr[mt], ad + 16384u);
            }
            #pragma unroll
            for (int bt = 0; bt < 2; bt++) {
                uint32_t bd = bb + 32768u + bBase[bt] + kb;
                LDM4(bhr[bt], bd);
                LDM4(blr[bt], bd + 16384u);
            }
            #pragma unroll
            for (int mt = 0; mt < 4; mt++)
                #pragma unroll
                for (int nt = 0; nt < 4; nt++) {
                    const int bt = nt >> 1, p = (nt & 1) * 2;
                    mma16816(acc[mt][nt], ahr[mt], bhr[bt][p], bhr[bt][p+1]);
                    mma16816(acc[mt][nt], ahr[mt], blr[bt][p], blr[bt][p+1]);
                    mma16816(acc[mt][nt], alr[mt], bhr[bt][p], bhr[bt][p+1]);
                }
        }
        __syncthreads();
    }

    {
        float* ep = (float*)sp;
        const int g = lane >> 2, tg = lane & 3;
        #pragma unroll
        for (int mt = 0; mt < 4; mt++)
            #pragma unroll
            for (int nt = 0; nt < 4; nt++) {
                int rr = wm * 64 + mt * 16 + g;
                int cc = wn * 32 + nt * 8 + tg * 2;
                ep[rr * 129 + cc]       = acc[mt][nt][0];
                ep[rr * 129 + cc + 1]   = acc[mt][nt][1];
                ep[(rr+8) * 129 + cc]   = acc[mt][nt][2];
                ep[(rr+8) * 129 + cc+1] = acc[mt][nt][3];
            }
    }
    __syncthreads();
    {
        float* ep = (float*)sp;
        for (int j = tid; j < 4096; j += 256) {
            int r = j >> 5;
            int c4 = (j & 31) << 2;
            int col = n0 + c4;
            size_t gbase = (size_t)(m0 + r) * N + col;
            float v[4];
            #pragma unroll
            for (int k = 0; k < 4; k++) {
                v[k] = ep[r * 129 + c4 + k];
                if (bias) v[k] += bias[col + k];
            }
            if (mode >= 1) {
                __nv_bfloat16 h[4], l[4];
                #pragma unroll
                for (int k = 0; k < 4; k++) {
                    if (mode == 1) v[k] = fmaxf(v[k], 0.f);
                    split2(v[k], h[k], l[k]);
                }
                reinterpret_cast<__nv_bfloat162*>(outh + gbase)[0] = __nv_bfloat162(h[0], h[1]);
                reinterpret_cast<__nv_bfloat162*>(outh + gbase)[1] = __nv_bfloat162(h[2], h[3]);
                reinterpret_cast<__nv_bfloat162*>(outl + gbase)[0] = __nv_bfloat162(l[0], l[1]);
                reinterpret_cast<__nv_bfloat162*>(outl + gbase)[1] = __nv_bfloat162(l[2], l[3]);
            } else {
                if (resid) {
                    float4 rr = *reinterpret_cast<const float4*>(resid + gbase);
                    v[0] += rr.x; v[1] += rr.y; v[2] += rr.z; v[3] += rr.w;
                }
                float4 o; o.x=v[0]; o.y=v[1]; o.z=v[2]; o.w=v[3];
                *reinterpret_cast<float4*>(outf + gbase) = o;
            }
        }
    }
}

// ---------------- HMMA fused attention ----------------
// 4 warps, 64 q-rows/block; K tiles of 64 keys, double-buffered cp.async.
// S = Q K^T via bf16 hi/lo x3; online softmax (FMA exp); P hi/lo in regs
// (C-frag -> A-frag identity); PV via ldmatrix.trans on V, hi/lo x3.
#define AT_SMEM (16384 + 2*32768 + 1024)
__global__ __launch_bounds__(128) void attn_kernel(
    const __nv_bfloat16* __restrict__ qkvh,
    const __nv_bfloat16* __restrict__ qkvl,
    const float* __restrict__ nmask,
    const float* __restrict__ mask,
    __nv_bfloat16* __restrict__ Oh,
    __nv_bfloat16* __restrict__ Ol) {
    extern __shared__ char dsm[];
    uint32_t u0 = smem_u32(dsm);
    uint32_t sb = u0 + ((1024u - (u0 & 1023u)) & 1023u);

    const int tid = threadIdx.x;
    const int wid = tid >> 5;
    const int lane = tid & 31;
    const int h  = blockIdx.x;
    const int q0 = blockIdx.y * 64;
    const int b  = blockIdx.z;
    const int g  = lane >> 2;
    const int t4 = lane & 3;
    const int sel = lane >> 3;
    const int rin = lane & 7;

    const size_t rs = 3 * ND;
    const size_t bh = (size_t)b * NT * rs + h * 192;

    // ---- Q load (hi/lo), swizzled SW128 rows of 128B ----
    {
        int mt = tid >> 6;            // 0=hi 1=lo
        int lt = tid & 63;
        int rb = lt >> 3;             // 0..7
        int cu = lt & 7;
        const __nv_bfloat16* src = (mt ? qkvl : qkvh) + bh + 64 + (size_t)q0 * rs + cu * 8;
        uint32_t dstb = sb + (uint32_t)mt * 8192u;
        #pragma unroll
        for (int i = 0; i < 8; i++) {
            int r = rb + 8 * i;
            CP_ASYNC16(dstb + (uint32_t)r * 128u + (((uint32_t)(cu ^ (r & 7))) << 4),
                       src + (size_t)r * rs);
        }
    }
    CP_COMMIT();

    // ---- K/V stage loader ----
    auto load_kv = [&](int kt, int s) {
        int mt = tid >> 5;            // 0=Kh 1=Kl 2=Vh 3=Vl
        int lt = tid & 31;
        int rb = lt >> 3;             // 0..3
        int cu = lt & 7;
        const __nv_bfloat16* src = ((mt & 1) ? qkvl : qkvh) + bh + (mt < 2 ? 128 : 0)
                                   + (size_t)kt * rs + cu * 8;
        uint32_t dstb = sb + 16384u + (uint32_t)s * 32768u + (uint32_t)mt * 8192u;
        #pragma unroll
        for (int i = 0; i < 16; i++) {
            int r = rb + 4 * i;
            CP_ASYNC16(dstb + (uint32_t)r * 128u + (((uint32_t)(cu ^ (r & 7))) << 4),
                       src + (size_t)r * rs);
        }
    };

    load_kv(0, 0);
    CP_COMMIT();
    CP_WAIT1();                  // Q group done (KV0 may be in flight)
    __syncthreads();

    // ---- preload Q A-fragments (whole DH=64 -> 4 k16 steps) ----
    uint32_t qa_h[4][4], qa_l[4][4];
    {
        const uint32_t aRow = (uint32_t)(wid * 16 + ((sel & 1) << 3) + rin) * 128u;
        const uint32_t aKB = (uint32_t)(sel >> 1) * 16u;
        #pragma unroll
        for (int ks = 0; ks < 4; ks++) {
            uint32_t ad = sb + aRow + (((uint32_t)ks * 32u + aKB) ^ ((uint32_t)rin << 4));
            LDM4(qa_h[ks], ad);
            LDM4(qa_l[ks], ad + 8192u);
        }
    }

    float of[8][4];
    #pragma unroll
    for (int j = 0; j < 8; j++) of[j][0]=of[j][1]=of[j][2]=of[j][3]=0.f;
    float mA = -1e30f, mB = -1e30f, lA = 0.f, lB = 0.f;

    const float* nmrow = nmask + (size_t)b * NT * NT + (size_t)(q0 + wid*16 + g) * NT + 2*t4;
    const float* mkrow = mask  + (size_t)b * NT * NT + (size_t)(q0 + wid*16 + g) * NT + 2*t4;

    const int bRow = ((sel >> 1) << 3) + rin;
    const uint32_t bKB = (uint32_t)(sel & 1) * 16u;
    const uint32_t xorv = (uint32_t)rin << 4;

    for (int it = 0; it < NT/64; ++it) {
        const int kt = it * 64;
        const int s = it & 1;
        if (it + 1 < NT/64) { load_kv(kt + 64, s ^ 1); CP_COMMIT(); CP_WAIT1(); }
        else                { CP_WAIT0(); }
        __syncthreads();

        const uint32_t kb = sb + 16384u + (uint32_t)s * 32768u;

        // ---- S = Q K^T (hi/lo x3) ----
        float sf[8][4];
        #pragma unroll
        for (int j = 0; j < 8; j++) sf[j][0]=sf[j][1]=sf[j][2]=sf[j][3]=0.f;
        #pragma unroll
        for (int ks = 0; ks < 4; ks++) {
            uint32_t khr[4][4], klr[4][4];
            const uint32_t ko = (((uint32_t)ks * 32u + bKB) ^ xorv);
            #pragma unroll
            for (int bt = 0; bt < 4; bt++) {
                uint32_t bd = kb + (uint32_t)(bt * 16 + bRow) * 128u + ko;
                LDM4(khr[bt], bd);
                LDM4(klr[bt], bd + 8192u);
            }
            #pragma unroll
            for (int nt = 0; nt < 8; nt++) {
                const int bt = nt >> 1, p = (nt & 1) * 2;
                mma16816(sf[nt], qa_h[ks], khr[bt][p], khr[bt][p+1]);
                mma16816(sf[nt], qa_h[ks], klr[bt][p], klr[bt][p+1]);
                mma16816(sf[nt], qa_l[ks], khr[bt][p], khr[bt][p+1]);
            }
        }

        // ---- scale + new_mask + online softmax ----
        const float* nmp = nmrow + kt;
        float rmA = -3e38f, rmB = -3e38f;
        #pragma unroll
        for (int j = 0; j < 8; j++) {
            float2 na = *reinterpret_cast<const float2*>(nmp + j*8);
            float2 nb = *reinterpret_cast<const float2*>(nmp + 8*NT + j*8);
            sf[j][0] = fmaf(sf[j][0], 0.125f, na.x);
            sf[j][1] = fmaf(sf[j][1], 0.125f, na.y);
            sf[j][2] = fmaf(sf[j][2], 0.125f, nb.x);
            sf[j][3] = fmaf(sf[j][3], 0.125f, nb.y);
            rmA = fmaxf(rmA, fmaxf(sf[j][0], sf[j][1]));
            rmB = fmaxf(rmB, fmaxf(sf[j][2], sf[j][3]));
        }
        rmA = fmaxf(rmA, __shfl_xor_sync(0xffffffffu, rmA, 1));
        rmA = fmaxf(rmA, __shfl_xor_sync(0xffffffffu, rmA, 2));
        rmB = fmaxf(rmB, __shfl_xor_sync(0xffffffffu, rmB, 1));
        rmB = fmaxf(rmB, __shfl_xor_sync(0xffffffffu, rmB, 2));
        float nmxA = fmaxf(mA, rmA), nmxB = fmaxf(mB, rmB);
        float corrA = fexp(mA - nmxA), corrB = fexp(mB - nmxB);
        mA = nmxA; mB = nmxB;

        float sumA = 0.f, sumB = 0.f;
        #pragma unroll
        for (int j = 0; j < 8; j++) {
            sf[j][0] = fexp(sf[j][0] - nmxA);
            sf[j][1] = fexp(sf[j][1] - nmxA);
            sf[j][2] = fexp(sf[j][2] - nmxB);
            sf[j][3] = fexp(sf[j][3] - nmxB);
            sumA += sf[j][0] + sf[j][1];
            sumB += sf[j][2] + sf[j][3];
        }
        sumA += __shfl_xor_sync(0xffffffffu, sumA, 1);
        sumA += __shfl_xor_sync(0xffffffffu, sumA, 2);
        sumB += __shfl_xor_sync(0xffffffffu, sumB, 1);
        sumB += __shfl_xor_sync(0xffffffffu, sumB, 2);
        lA = lA * corrA + sumA;
        lB = lB * corrB + sumB;

        // ---- P = exp * mask, split hi/lo, pack into A-fragments ----
        const float* mkp = mkrow + kt;
        uint32_t pah[4][4], pal[4][4];
        #pragma unroll
        for (int j = 0; j < 8; j++) {
            float2 ma_ = *reinterpret_cast<const float2*>(mkp + j*8);
            float2 mb_ = *reinterpret_cast<const float2*>(mkp + 8*NT + j*8);
            float p0 = sf[j][0] * ma_.x, p1 = sf[j][1] * ma_.y;
            float p2 = sf[j][2] * mb_.x, p3 = sf[j][3] * mb_.y;
            __nv_bfloat16 h0,h1,h2,h3,l0,l1,l2,l3;
            split2(p0,h0,l0); split2(p1,h1,l1); split2(p2,h2,l2); split2(p3,h3,l3);
            const int jj = j >> 1, q = (j & 1) * 2;
            pah[jj][q]   = pack_bf2(h0, h1);
            pah[jj][q+1] = pack_bf2(h2, h3);
            pal[jj][q]   = pack_bf2(l0, l1);
            pal[jj][q+1] = pack_bf2(l2, l3);
        }

        // ---- rescale O ----
        #pragma unroll
        for (int j = 0; j < 8; j++) {
            of[j][0] *= corrA; of[j][1] *= corrA;
            of[j][2] *= corrB; of[j][3] *= corrB;
        }

        // ---- O += P V (hi/lo x3), V via ldmatrix.trans ----
        #pragma unroll
        for (int kk = 0; kk < 4; kk++) {
            uint32_t vh[4][4], vl[4][4];
            const int rr = kk * 16 + ((sel & 1) << 3) + rin;
            #pragma unroll
            for (int nt = 0; nt < 4; nt++) {
                uint32_t cu_ = (uint32_t)(nt * 2 + (sel >> 1));
                uint32_t vd = kb + 16384u + (uint32_t)rr * 128u + ((cu_ ^ (uint32_t)(rr & 7)) << 4);
                LDM4T(vh[nt], vd);
                LDM4T(vl[nt], vd + 8192u);
            }
            #pragma unroll
            for (int j = 0; j < 8; j++) {
                const int bt = j >> 1, p = (j & 1) * 2;
                mma16816(of[j], pah[kk], vh[bt][p], vh[bt][p+1]);
                mma16816(of[j], pah[kk], vl[bt][p], vl[bt][p+1]);
                mma16816(of[j], pal[kk], vh[bt][p], vh[bt][p+1]);
            }
        }
        __syncthreads();
    }

    // ---- normalize, leaky_relu, split, store ----
    const float invA = 1.0f / lA, invB = 1.0f / lB;
    size_t obase = (size_t)(b*NT + q0 + wid*16 + g) * ND + h*64 + 2*t4;
    #pragma unroll
    for (int j = 0; j < 8; j++) {
        float o0 = of[j][0] * invA, o1 = of[j][1] * invA;
        float o2 = of[j][2] * invB, o3 = of[j][3] * invB;
        o0 = o0 >= 0.f ? o0 : 0.01f*o0;
        o1 = o1 >= 0.f ? o1 : 0.01f*o1;
        o2 = o2 >= 0.f ? o2 : 0.01f*o2;
        o3 = o3 >= 0.f ? o3 : 0.01f*o3;
        __nv_bfloat16 h0,h1,h2,h3,l0,l1,l2,l3;
        split2(o0,h0,l0); split2(o1,h1,l1); split2(o2,h2,l2); split2(o3,h3,l3);
        *reinterpret_cast<__nv_bfloat162*>(Oh + obase + j*8)            = __nv_bfloat162(h0,h1);
        *reinterpret_cast<__nv_bfloat162*>(Oh + obase + 8*ND + j*8)     = __nv_bfloat162(h2,h3);
        *reinterpret_cast<__nv_bfloat162*>(Ol + obase + j*8)            = __nv_bfloat162(l0,l1);
        *reinterpret_cast<__nv_bfloat162*>(Ol + obase + 8*ND + j*8)     = __nv_bfloat162(l2,l3);
    }
}

// ---------------- launch ----------------
#define GT_SMEM (132096)

extern "C" void kernel_launch(void* const* d_in, const int* in_sizes, int n_in,
                              void* d_out, int out_size) {
    const float* Z     = (const float*)d_in[0];
    const float* nmask = (const float*)d_in[1];
    const float* mask  = (const float*)d_in[2];
    const float* ln1g  = (const float*)d_in[3];
    const float* ln1b  = (const float*)d_in[4];
    const float* qkvw  = (const float*)d_in[5];
    const float* qkvb  = (const float*)d_in[6];
    const float* ow    = (const float*)d_in[7];
    const float* ln2g  = (const float*)d_in[8];
    const float* ln2b  = (const float*)d_in[9];
    const float* p1w   = (const float*)d_in[10];
    const float* p1b   = (const float*)d_in[11];
    const float* p2w   = (const float*)d_in[12];
    const float* p2b   = (const float*)d_in[13];
    float* out = (float*)d_out;

    __nv_bfloat16 *Znh,*Znl,*qkvh,*qkvl,*ah,*al,*Zn2h,*Zn2l,*hh,*hl;
    __nv_bfloat16 *wqh,*wql,*woh,*wol,*w1h,*w1l,*w2h,*w2l;
    float *Z1;
    cudaGetSymbolAddress((void**)&Znh,  g_Znh);  cudaGetSymbolAddress((void**)&Znl,  g_Znl);
    cudaGetSymbolAddress((void**)&qkvh, g_qkvh); cudaGetSymbolAddress((void**)&qkvl, g_qkvl);
    cudaGetSymbolAddress((void**)&ah,   g_ah);   cudaGetSymbolAddress((void**)&al,   g_al);
    cudaGetSymbolAddress((void**)&Z1,   g_Z1);
    cudaGetSymbolAddress((void**)&Zn2h, g_Zn2h); cudaGetSymbolAddress((void**)&Zn2l, g_Zn2l);
    cudaGetSymbolAddress((void**)&hh,   g_hh);   cudaGetSymbolAddress((void**)&hl,   g_hl);
    cudaGetSymbolAddress((void**)&wqh,  g_wqh);  cudaGetSymbolAddress((void**)&wql,  g_wql);
    cudaGetSymbolAddress((void**)&woh,  g_woh);  cudaGetSymbolAddress((void**)&wol,  g_wol);
    cudaGetSymbolAddress((void**)&w1h,  g_w1h);  cudaGetSymbolAddress((void**)&w1l,  g_w1l);
    cudaGetSymbolAddress((void**)&w2h,  g_w2h);  cudaGetSymbolAddress((void**)&w2l,  g_w2l);

    cudaFuncSetAttribute(gemm_tc, cudaFuncAttributeMaxDynamicSharedMemorySize, GT_SMEM);
    cudaFuncSetAttribute(attn_kernel, cudaFuncAttributeMaxDynamicSharedMemorySize, AT_SMEM);

    split_kernel<<<(3*ND*ND/4 + 255)/256, 256>>>(qkvw, wqh, wql, 3*ND*ND/4);
    split_kernel<<<(ND*ND/4 + 255)/256, 256>>>(ow, woh, wol, ND*ND/4);
    split_kernel<<<(NDI*ND/4 + 255)/256, 256>>>(p1w, w1h, w1l, NDI*ND/4);
    split_kernel<<<(ND*NDI/4 + 255)/256, 256>>>(p2w, w2h, w2l, ND*NDI/4);

    ln_kernel<<<NM, 256>>>(Z, ln1g, ln1b, Znh, Znl);
    gemm_tc<<<dim3(3*ND/128, NM/128), 256, GT_SMEM>>>(
        Znh, Znl, wqh, wql, qkvb, nullptr, nullptr, qkvh, qkvl, NM, 3*ND, ND, 2);
    attn_kernel<<<dim3(NH, NT/64, NB), 128, AT_SMEM>>>(qkvh, qkvl, nmask, mask, ah, al);
    gemm_tc<<<dim3(ND/128, NM/128), 256, GT_SMEM>>>(
        ah, al, woh, wol, nullptr, Z, Z1, nullptr, nullptr, NM, ND, ND, 0);
    ln_kernel<<<NM, 256>>>(Z1, ln2g, ln2b, Zn2h, Zn2l);
    gemm_tc<<<dim3(NDI/128, NM/128), 256, GT_SMEM>>>(
        Zn2h, Zn2l, w1h, w1l, p1b, nullptr, nullptr, hh, hl, NM, NDI, ND, 1);
    gemm_tc<<<dim3(ND/128, NM/128), 256, GT_SMEM>>>(
        hh, hl, w2h, w2l, p2b, Z1, out, nullptr, nullptr, NM, ND, NDI, 0);
}

// round 8
// speedup vs baseline: 2.9961x; 1.0880x over previous
#include <cuda_runtime.h>
#include <cuda_bf16.h>
#include <math.h>
#include <cstdint>

#define NB 2
#define NT 2048
#define ND 1024
#define NH 16
#define NDI 4096
#define NM (NB*NT)          // 4096 rows
#define EPS_ 1e-5f

// ---------------- scratch (no cudaMalloc allowed) ----------------
__device__ __nv_bfloat16 g_Znh [(size_t)NM * ND];
__device__ __nv_bfloat16 g_Znl [(size_t)NM * ND];
__device__ __nv_bfloat16 g_qkvh[(size_t)NM * 3 * ND];
__device__ __nv_bfloat16 g_qkvl[(size_t)NM * 3 * ND];
__device__ __nv_bfloat16 g_ah  [(size_t)NM * ND];
__device__ __nv_bfloat16 g_al  [(size_t)NM * ND];
__device__ float         g_Z1  [(size_t)NM * ND];
__device__ __nv_bfloat16 g_Zn2h[(size_t)NM * ND];
__device__ __nv_bfloat16 g_Zn2l[(size_t)NM * ND];
__device__ __nv_bfloat16 g_hh  [(size_t)NM * NDI];
__device__ __nv_bfloat16 g_hl  [(size_t)NM * NDI];
__device__ __nv_bfloat16 g_wqh [(size_t)3*ND*ND];
__device__ __nv_bfloat16 g_wql [(size_t)3*ND*ND];
__device__ __nv_bfloat16 g_woh [(size_t)ND*ND];
__device__ __nv_bfloat16 g_wol [(size_t)ND*ND];
__device__ __nv_bfloat16 g_w1h [(size_t)NDI*ND];
__device__ __nv_bfloat16 g_w1l [(size_t)NDI*ND];
__device__ __nv_bfloat16 g_w2h [(size_t)ND*NDI];
__device__ __nv_bfloat16 g_w2l [(size_t)ND*NDI];

// ---------------- helpers ----------------
__device__ __forceinline__ uint32_t smem_u32(const void* p) {
    uint32_t a;
    asm("{ .reg .u64 t; cvta.to.shared.u64 t, %1; cvt.u32.u64 %0, t; }" : "=r"(a) : "l"(p));
    return a;
}

__device__ __forceinline__ uint32_t pack_bf2(__nv_bfloat16 lo, __nv_bfloat16 hi) {
    return (uint32_t)__bfloat16_as_ushort(lo) | ((uint32_t)__bfloat16_as_ushort(hi) << 16);
}

#define LDM4(r, addr) \
    asm volatile("ldmatrix.sync.aligned.m8n8.x4.shared.b16 {%0,%1,%2,%3}, [%4];" \
        : "=r"((r)[0]), "=r"((r)[1]), "=r"((r)[2]), "=r"((r)[3]) : "r"(addr))
#define LDM4T(r, addr) \
    asm volatile("ldmatrix.sync.aligned.m8n8.x4.trans.shared.b16 {%0,%1,%2,%3}, [%4];" \
        : "=r"((r)[0]), "=r"((r)[1]), "=r"((r)[2]), "=r"((r)[3]) : "r"(addr))

__device__ __forceinline__ void mma16816(float* c, const uint32_t* a,
                                         uint32_t b0, uint32_t b1) {
    asm volatile("mma.sync.aligned.m16n8k16.row.col.f32.bf16.bf16.f32 "
        "{%0,%1,%2,%3}, {%4,%5,%6,%7}, {%8,%9}, {%0,%1,%2,%3};"
        : "+f"(c[0]), "+f"(c[1]), "+f"(c[2]), "+f"(c[3])
        : "r"(a[0]), "r"(a[1]), "r"(a[2]), "r"(a[3]), "r"(b0), "r"(b1));
}

#define CP_ASYNC16(dst, src) \
    asm volatile("cp.async.cg.shared.global [%0], [%1], 16;" :: "r"(dst), "l"(src) : "memory")
#define CP_COMMIT() asm volatile("cp.async.commit_group;" ::: "memory")
#define CP_WAIT1()  asm volatile("cp.async.wait_group 1;" ::: "memory")
#define CP_WAIT0()  asm volatile("cp.async.wait_group 0;" ::: "memory")

__device__ __forceinline__ void split2(float x, __nv_bfloat16& h, __nv_bfloat16& l) {
    h = __float2bfloat16(x);
    l = __float2bfloat16(x - __bfloat162float(h));
}

// fast exp via FMA (no MUFU): rel err ~2e-8
__device__ __forceinline__ float fexp(float x) {
    x = fmaxf(x, -87.0f);
    float t = fmaf(x, 1.4426950408889634f, 12582912.0f);
    int   i = __float_as_int(t) - 0x4B400000;
    float fi = t - 12582912.0f;
    float f  = fmaf(x, 1.4426950408889634f, -fi);
    float p  = 1.3333558146e-3f;
    p = fmaf(p, f, 9.6181291076e-3f);
    p = fmaf(p, f, 5.5504108664e-2f);
    p = fmaf(p, f, 2.4022650695910071e-1f);
    p = fmaf(p, f, 6.9314718055994531e-1f);
    p = fmaf(p, f, 1.0f);
    return __int_as_float(__float_as_int(p) + (i << 23));
}

// ---------------- merged weight split: fp32 -> (hi, lo) bf16, 4 tensors ----------------
#define SP_N0 786432              // qkv_w  (3*ND*ND/4)
#define SP_N1 262144              // o_w    (ND*ND/4)
#define SP_N2 1048576             // p1_w   (NDI*ND/4)
#define SP_N3 1048576             // p2_w   (ND*NDI/4)
__global__ void split4_kernel(const float* __restrict__ X0, __nv_bfloat16* __restrict__ H0, __nv_bfloat16* __restrict__ L0,
                              const float* __restrict__ X1, __nv_bfloat16* __restrict__ H1, __nv_bfloat16* __restrict__ L1,
                              const float* __restrict__ X2, __nv_bfloat16* __restrict__ H2, __nv_bfloat16* __restrict__ L2,
                              const float* __restrict__ X3, __nv_bfloat16* __restrict__ H3, __nv_bfloat16* __restrict__ L3) {
    int i = blockIdx.x * blockDim.x + threadIdx.x;
    const float* X; __nv_bfloat16 *H, *L;
    if      (i < SP_N0)                         { X = X0; H = H0; L = L0; }
    else if (i < SP_N0+SP_N1)                   { X = X1; H = H1; L = L1; i -= SP_N0; }
    else if (i < SP_N0+SP_N1+SP_N2)             { X = X2; H = H2; L = L2; i -= SP_N0+SP_N1; }
    else if (i < SP_N0+SP_N1+SP_N2+SP_N3)       { X = X3; H = H3; L = L3; i -= SP_N0+SP_N1+SP_N2; }
    else return;
    float4 v = reinterpret_cast<const float4*>(X)[i];
    __nv_bfloat16 h0, h1, h2, h3, l0, l1, l2, l3;
    split2(v.x, h0, l0); split2(v.y, h1, l1); split2(v.z, h2, l2); split2(v.w, h3, l3);
    reinterpret_cast<__nv_bfloat162*>(H)[2*i]   = __nv_bfloat162(h0, h1);
    reinterpret_cast<__nv_bfloat162*>(H)[2*i+1] = __nv_bfloat162(h2, h3);
    reinterpret_cast<__nv_bfloat162*>(L)[2*i]   = __nv_bfloat162(l0, l1);
    reinterpret_cast<__nv_bfloat162*>(L)[2*i+1] = __nv_bfloat162(l2, l3);
}

// ---------------- LayerNorm -> (hi, lo) bf16 ----------------
__global__ void ln_kernel(const float* __restrict__ X,
                          const float* __restrict__ g,
                          const float* __restrict__ b,
                          __nv_bfloat16* __restrict__ Yh,
                          __nv_bfloat16* __restrict__ Yl) {
    int row = blockIdx.x;
    int t = threadIdx.x;
    float4 v = reinterpret_cast<const float4*>(X + (size_t)row * ND)[t];
    float s  = v.x + v.y + v.z + v.w;
    float sq = v.x*v.x + v.y*v.y + v.z*v.z + v.w*v.w;
    #pragma unroll
    for (int o = 16; o > 0; o >>= 1) {
        s  += __shfl_xor_sync(0xffffffffu, s,  o);
        sq += __shfl_xor_sync(0xffffffffu, sq, o);
    }
    __shared__ float ss[8], ssq[8];
    int w = t >> 5, l = t & 31;
    if (l == 0) { ss[w] = s; ssq[w] = sq; }
    __syncthreads();
    if (w == 0) {
        s = ss[l & 7]; sq = ssq[l & 7];
        #pragma unroll
        for (int o = 4; o > 0; o >>= 1) {
            s  += __shfl_xor_sync(0xffffffffu, s,  o);
            sq += __shfl_xor_sync(0xffffffffu, sq, o);
        }
        if (l == 0) { ss[0] = s; ssq[0] = sq; }
    }
    __syncthreads();
    s = ss[0]; sq = ssq[0];
    float mu  = s * (1.0f / ND);
    float var = sq * (1.0f / ND) - mu * mu;
    float rstd = rsqrtf(var + EPS_);
    float4 gv = reinterpret_cast<const float4*>(g)[t];
    float4 bv = reinterpret_cast<const float4*>(b)[t];
    float y0 = (v.x - mu) * rstd * gv.x + bv.x;
    float y1 = (v.y - mu) * rstd * gv.y + bv.y;
    float y2 = (v.z - mu) * rstd * gv.z + bv.z;
    float y3 = (v.w - mu) * rstd * gv.w + bv.w;
    __nv_bfloat16 h0,h1,h2,h3,l0,l1,l2,l3;
    split2(y0,h0,l0); split2(y1,h1,l1); split2(y2,h2,l2); split2(y3,h3,l3);
    size_t base = (size_t)row * ND + t * 4;
    reinterpret_cast<__nv_bfloat162*>(Yh + base)[0] = __nv_bfloat162(h0, h1);
    reinterpret_cast<__nv_bfloat162*>(Yh + base)[1] = __nv_bfloat162(h2, h3);
    reinterpret_cast<__nv_bfloat162*>(Yl + base)[0] = __nv_bfloat162(l0, l1);
    reinterpret_cast<__nv_bfloat162*>(Yl + base)[1] = __nv_bfloat162(l2, l3);
}

// ---------------- HMMA bf16x3 GEMM:  C = A @ W^T ----------------
// mode 0: outf = acc(+bias)(+resid); mode 1: relu(acc+bias)->(h,l); mode 2: (acc+bias)->(h,l)
#define GT_BUF 65536u
__global__ __launch_bounds__(256, 1) void gemm_tc(
    const __nv_bfloat16* __restrict__ Ah, const __nv_bfloat16* __restrict__ Al,
    const __nv_bfloat16* __restrict__ Bh, const __nv_bfloat16* __restrict__ Bl,
    const float* __restrict__ bias, const float* __restrict__ resid,
    float* __restrict__ outf, __nv_bfloat16* __restrict__ outh,
    __nv_bfloat16* __restrict__ outl,
    int M, int N, int K, int mode) {
    extern __shared__ char dsm[];

    const int tid  = threadIdx.x;
    const int wid  = tid >> 5;
    const int lane = tid & 31;
    const int m0 = blockIdx.y * 128;
    const int n0 = blockIdx.x * 128;
    const int wm = wid >> 2;
    const int wn = wid & 3;

    uint32_t u0 = smem_u32(dsm);
    uint32_t pad = (1024u - (u0 & 1023u)) & 1023u;
    char* sp = dsm + pad;
    uint32_t smem_al = u0 + pad;

    const int t  = tid >> 6;
    const int lt = tid & 63;
    const int r0 = lt >> 3;
    const int cu = lt & 7;
    const __nv_bfloat16* srcs[4] = {
        Ah + (size_t)m0 * K, Al + (size_t)m0 * K,
        Bh + (size_t)n0 * K, Bl + (size_t)n0 * K };
    const char* tsrc = (const char*)srcs[t] + (size_t)r0 * K * 2 + cu * 16;
    const size_t rstride8 = (size_t)8 * K * 2;
    const uint32_t toff = (uint32_t)t * 16384u;

    auto load_chunk = [&](int c, int b) {
        const char* src = tsrc + (size_t)c * 128;
        uint32_t dstb = smem_al + (uint32_t)b * GT_BUF + toff;
        #pragma unroll
        for (int i = 0; i < 16; i++) {
            uint32_t byte = (uint32_t)(r0 + 8 * i) * 128u + (uint32_t)cu * 16u;
            uint32_t sw = byte ^ ((byte >> 3) & 0x70u);
            CP_ASYNC16(dstb + sw, src + (size_t)i * rstride8);
        }
    };

    const int sel = lane >> 3;
    const int rin = lane & 7;
    const int aRowOff = ((sel & 1) << 3) + rin;
    const uint32_t aKB = (uint32_t)(sel >> 1) * 16u;
    const int bRowOff = ((sel >> 1) << 3) + rin;
    const uint32_t bKB = (uint32_t)(sel & 1) * 16u;
    const uint32_t xorv = (uint32_t)rin << 4;

    uint32_t aBase[4], bBase[2];
    #pragma unroll
    for (int mt = 0; mt < 4; mt++)
        aBase[mt] = (uint32_t)(wm * 64 + mt * 16 + aRowOff) * 128u;
    #pragma unroll
    for (int bt = 0; bt < 2; bt++)
        bBase[bt] = (uint32_t)(wn * 32 + bt * 16 + bRowOff) * 128u;

    float acc[4][4][4];
    #pragma unroll
    for (int i = 0; i < 4; i++)
        #pragma unroll
        for (int j = 0; j < 4; j++)
            acc[i][j][0]=acc[i][j][1]=acc[i][j][2]=acc[i][j][3]=0.f;

    const int nc = K >> 6;
    load_chunk(0, 0);
    CP_COMMIT();

    for (int c = 0; c < nc; ++c) {
        if (c + 1 < nc) { load_chunk(c + 1, (c + 1) & 1); CP_COMMIT(); CP_WAIT1(); }
        else            { CP_WAIT0(); }
        __syncthreads();

        const uint32_t bb = smem_al + (uint32_t)(c & 1) * GT_BUF;
        #pragma unroll
        for (int ks = 0; ks < 4; ks++) {
            uint32_t ahr[4][4], alr[4][4], bhr[2][4], blr[2][4];
            const uint32_t ka = ((uint32_t)ks * 32u + aKB) ^ xorv;
            const uint32_t kb = ((uint32_t)ks * 32u + bKB) ^ xorv;
            #pragma unroll
            for (int mt = 0; mt < 4; mt++) {
                uint32_t ad = bb + aBase[mt] + ka;
                LDM4(ahr[mt], ad);
                LDM4(alr[mt], ad + 16384u);
            }
            #pragma unroll
            for (int bt = 0; bt < 2; bt++) {
                uint32_t bd = bb + 32768u + bBase[bt] + kb;
                LDM4(bhr[bt], bd);
                LDM4(blr[bt], bd + 16384u);
            }
            #pragma unroll
            for (int mt = 0; mt < 4; mt++)
                #pragma unroll
                for (int nt = 0; nt < 4; nt++) {
                    const int bt = nt >> 1, p = (nt & 1) * 2;
                    mma16816(acc[mt][nt], ahr[mt], bhr[bt][p], bhr[bt][p+1]);
                    mma16816(acc[mt][nt], ahr[mt], blr[bt][p], blr[bt][p+1]);
                    mma16816(acc[mt][nt], alr[mt], bhr[bt][p], bhr[bt][p+1]);
                }
        }
        __syncthreads();
    }

    {
        float* ep = (float*)sp;
        const int g = lane >> 2, tg = lane & 3;
        #pragma unroll
        for (int mt = 0; mt < 4; mt++)
            #pragma unroll
            for (int nt = 0; nt < 4; nt++) {
                int rr = wm * 64 + mt * 16 + g;
                int cc = wn * 32 + nt * 8 + tg * 2;
                ep[rr * 129 + cc]       = acc[mt][nt][0];
                ep[rr * 129 + cc + 1]   = acc[mt][nt][1];
                ep[(rr+8) * 129 + cc]   = acc[mt][nt][2];
                ep[(rr+8) * 129 + cc+1] = acc[mt][nt][3];
            }
    }
    __syncthreads();
    {
        float* ep = (float*)sp;
        for (int j = tid; j < 4096; j += 256) {
            int r = j >> 5;
            int c4 = (j & 31) << 2;
            int col = n0 + c4;
            size_t gbase = (size_t)(m0 + r) * N + col;
            float v[4];
            #pragma unroll
            for (int k = 0; k < 4; k++) {
                v[k] = ep[r * 129 + c4 + k];
                if (bias) v[k] += bias[col + k];
            }
            if (mode >= 1) {
                __nv_bfloat16 h[4], l[4];
                #pragma unroll
                for (int k = 0; k < 4; k++) {
                    if (mode == 1) v[k] = fmaxf(v[k], 0.f);
                    split2(v[k], h[k], l[k]);
                }
                reinterpret_cast<__nv_bfloat162*>(outh + gbase)[0] = __nv_bfloat162(h[0], h[1]);
                reinterpret_cast<__nv_bfloat162*>(outh + gbase)[1] = __nv_bfloat162(h[2], h[3]);
                reinterpret_cast<__nv_bfloat162*>(outl + gbase)[0] = __nv_bfloat162(l[0], l[1]);
                reinterpret_cast<__nv_bfloat162*>(outl + gbase)[1] = __nv_bfloat162(l[2], l[3]);
            } else {
                if (resid) {
                    float4 rr = *reinterpret_cast<const float4*>(resid + gbase);
                    v[0] += rr.x; v[1] += rr.y; v[2] += rr.z; v[3] += rr.w;
                }
                float4 o; o.x=v[0]; o.y=v[1]; o.z=v[2]; o.w=v[3];
                *reinterpret_cast<float4*>(outf + gbase) = o;
            }
        }
    }
}

// ---------------- HMMA fused attention (2 CTAs/SM) ----------------
#define AT_SMEM (16384 + 2*32768 + 1024)
__global__ __launch_bounds__(128, 2) void attn_kernel(
    const __nv_bfloat16* __restrict__ qkvh,
    const __nv_bfloat16* __restrict__ qkvl,
    const float* __restrict__ nmask,
    const float* __restrict__ mask,
    __nv_bfloat16* __restrict__ Oh,
    __nv_bfloat16* __restrict__ Ol) {
    extern __shared__ char dsm[];
    uint32_t u0 = smem_u32(dsm);
    uint32_t sb = u0 + ((1024u - (u0 & 1023u)) & 1023u);

    const int tid = threadIdx.x;
    const int wid = tid >> 5;
    const int lane = tid & 31;
    const int h  = blockIdx.x;
    const int q0 = blockIdx.y * 64;
    const int b  = blockIdx.z;
    const int g  = lane >> 2;
    const int t4 = lane & 3;
    const int sel = lane >> 3;
    const int rin = lane & 7;

    const size_t rs = 3 * ND;
    const size_t bh = (size_t)b * NT * rs + h * 192;

    // ---- Q load (hi/lo), swizzled SW128 rows of 128B ----
    {
        int mt = tid >> 6;            // 0=hi 1=lo
        int lt = tid & 63;
        int rb = lt >> 3;             // 0..7
        int cu = lt & 7;
        const __nv_bfloat16* src = (mt ? qkvl : qkvh) + bh + 64 + (size_t)q0 * rs + cu * 8;
        uint32_t dstb = sb + (uint32_t)mt * 8192u;
        #pragma unroll
        for (int i = 0; i < 8; i++) {
            int r = rb + 8 * i;
            CP_ASYNC16(dstb + (uint32_t)r * 128u + (((uint32_t)(cu ^ (r & 7))) << 4),
                       src + (size_t)r * rs);
        }
    }
    CP_COMMIT();

    // ---- K/V stage loader ----
    auto load_kv = [&](int kt, int s) {
        int mt = tid >> 5;            // 0=Kh 1=Kl 2=Vh 3=Vl
        int lt = tid & 31;
        int rb = lt >> 3;             // 0..3
        int cu = lt & 7;
        const __nv_bfloat16* src = ((mt & 1) ? qkvl : qkvh) + bh + (mt < 2 ? 128 : 0)
                                   + (size_t)kt * rs + cu * 8;
        uint32_t dstb = sb + 16384u + (uint32_t)s * 32768u + (uint32_t)mt * 8192u;
        #pragma unroll
        for (int i = 0; i < 16; i++) {
            int r = rb + 4 * i;
            CP_ASYNC16(dstb + (uint32_t)r * 128u + (((uint32_t)(cu ^ (r & 7))) << 4),
                       src + (size_t)r * rs);
        }
    };

    load_kv(0, 0);
    CP_COMMIT();
    CP_WAIT1();                  // Q group done (KV0 may be in flight)
    __syncthreads();

    // ---- preload Q A-fragments (whole DH=64 -> 4 k16 steps) ----
    uint32_t qa_h[4][4], qa_l[4][4];
    {
        const uint32_t aRow = (uint32_t)(wid * 16 + ((sel & 1) << 3) + rin) * 128u;
        const uint32_t aKB = (uint32_t)(sel >> 1) * 16u;
        #pragma unroll
        for (int ks = 0; ks < 4; ks++) {
            uint32_t ad = sb + aRow + (((uint32_t)ks * 32u + aKB) ^ ((uint32_t)rin << 4));
            LDM4(qa_h[ks], ad);
            LDM4(qa_l[ks], ad + 8192u);
        }
    }

    float of[8][4];
    #pragma unroll
    for (int j = 0; j < 8; j++) of[j][0]=of[j][1]=of[j][2]=of[j][3]=0.f;
    float mA = -1e30f, mB = -1e30f, lA = 0.f, lB = 0.f;

    const float* nmrow = nmask + (size_t)b * NT * NT + (size_t)(q0 + wid*16 + g) * NT + 2*t4;
    const float* mkrow = mask  + (size_t)b * NT * NT + (size_t)(q0 + wid*16 + g) * NT + 2*t4;

    const int bRow = ((sel >> 1) << 3) + rin;
    const uint32_t bKB = (uint32_t)(sel & 1) * 16u;
    const uint32_t xorv = (uint32_t)rin << 4;

    for (int it = 0; it < NT/64; ++it) {
        const int kt = it * 64;
        const int s = it & 1;
        if (it + 1 < NT/64) { load_kv(kt + 64, s ^ 1); CP_COMMIT(); CP_WAIT1(); }
        else                { CP_WAIT0(); }
        __syncthreads();

        const uint32_t kb = sb + 16384u + (uint32_t)s * 32768u;

        // ---- S = Q K^T (hi/lo x3) ----
        float sf[8][4];
        #pragma unroll
        for (int j = 0; j < 8; j++) sf[j][0]=sf[j][1]=sf[j][2]=sf[j][3]=0.f;
        #pragma unroll
        for (int ks = 0; ks < 4; ks++) {
            uint32_t khr[4][4], klr[4][4];
            const uint32_t ko = (((uint32_t)ks * 32u + bKB) ^ xorv);
            #pragma unroll
            for (int bt = 0; bt < 4; bt++) {
                uint32_t bd = kb + (uint32_t)(bt * 16 + bRow) * 128u + ko;
                LDM4(khr[bt], bd);
                LDM4(klr[bt], bd + 8192u);
            }
            #pragma unroll
            for (int nt = 0; nt < 8; nt++) {
                const int bt = nt >> 1, p = (nt & 1) * 2;
                mma16816(sf[nt], qa_h[ks], khr[bt][p], khr[bt][p+1]);
                mma16816(sf[nt], qa_h[ks], klr[bt][p], klr[bt][p+1]);
                mma16816(sf[nt], qa_l[ks], khr[bt][p], khr[bt][p+1]);
            }
        }

        // ---- scale + new_mask + online softmax ----
        const float* nmp = nmrow + kt;
        float rmA = -3e38f, rmB = -3e38f;
        #pragma unroll
        for (int j = 0; j < 8; j++) {
            float2 na = *reinterpret_cast<const float2*>(nmp + j*8);
            float2 nb = *reinterpret_cast<const float2*>(nmp + 8*NT + j*8);
            sf[j][0] = fmaf(sf[j][0], 0.125f, na.x);
            sf[j][1] = fmaf(sf[j][1], 0.125f, na.y);
            sf[j][2] = fmaf(sf[j][2], 0.125f, nb.x);
            sf[j][3] = fmaf(sf[j][3], 0.125f, nb.y);
            rmA = fmaxf(rmA, fmaxf(sf[j][0], sf[j][1]));
            rmB = fmaxf(rmB, fmaxf(sf[j][2], sf[j][3]));
        }
        rmA = fmaxf(rmA, __shfl_xor_sync(0xffffffffu, rmA, 1));
        rmA = fmaxf(rmA, __shfl_xor_sync(0xffffffffu, rmA, 2));
        rmB = fmaxf(rmB, __shfl_xor_sync(0xffffffffu, rmB, 1));
        rmB = fmaxf(rmB, __shfl_xor_sync(0xffffffffu, rmB, 2));
        float nmxA = fmaxf(mA, rmA), nmxB = fmaxf(mB, rmB);
        float corrA = fexp(mA - nmxA), corrB = fexp(mB - nmxB);
        mA = nmxA; mB = nmxB;

        float sumA = 0.f, sumB = 0.f;
        #pragma unroll
        for (int j = 0; j < 8; j++) {
            sf[j][0] = fexp(sf[j][0] - nmxA);
            sf[j][1] = fexp(sf[j][1] - nmxA);
            sf[j][2] = fexp(sf[j][2] - nmxB);
            sf[j][3] = fexp(sf[j][3] - nmxB);
            sumA += sf[j][0] + sf[j][1];
            sumB += sf[j][2] + sf[j][3];
        }
        sumA += __shfl_xor_sync(0xffffffffu, sumA, 1);
        sumA += __shfl_xor_sync(0xffffffffu, sumA, 2);
        sumB += __shfl_xor_sync(0xffffffffu, sumB, 1);
        sumB += __shfl_xor_sync(0xffffffffu, sumB, 2);
        lA = lA * corrA + sumA;
        lB = lB * corrB + sumB;

        // ---- P = exp * mask, split hi/lo, pack into A-fragments ----
        const float* mkp = mkrow + kt;
        uint32_t pah[4][4], pal[4][4];
        #pragma unroll
        for (int j = 0; j < 8; j++) {
            float2 ma_ = *reinterpret_cast<const float2*>(mkp + j*8);
            float2 mb_ = *reinterpret_cast<const float2*>(mkp + 8*NT + j*8);
            float p0 = sf[j][0] * ma_.x, p1 = sf[j][1] * ma_.y;
            float p2 = sf[j][2] * mb_.x, p3 = sf[j][3] * mb_.y;
            __nv_bfloat16 h0,h1,h2,h3,l0,l1,l2,l3;
            split2(p0,h0,l0); split2(p1,h1,l1); split2(p2,h2,l2); split2(p3,h3,l3);
            const int jj = j >> 1, q = (j & 1) * 2;
            pah[jj][q]   = pack_bf2(h0, h1);
            pah[jj][q+1] = pack_bf2(h2, h3);
            pal[jj][q]   = pack_bf2(l0, l1);
            pal[jj][q+1] = pack_bf2(l2, l3);
        }

        // ---- rescale O ----
        #pragma unroll
        for (int j = 0; j < 8; j++) {
            of[j][0] *= corrA; of[j][1] *= corrA;
            of[j][2] *= corrB; of[j][3] *= corrB;
        }

        // ---- O += P V (hi/lo x3), V via ldmatrix.trans ----
        #pragma unroll
        for (int kk = 0; kk < 4; kk++) {
            uint32_t vh[4][4], vl[4][4];
            const int rr = kk * 16 + ((sel & 1) << 3) + rin;
            #pragma unroll
            for (int nt = 0; nt < 4; nt++) {
                uint32_t cu_ = (uint32_t)(nt * 2 + (sel >> 1));
                uint32_t vd = kb + 16384u + (uint32_t)rr * 128u + ((cu_ ^ (uint32_t)(rr & 7)) << 4);
                LDM4T(vh[nt], vd);
                LDM4T(vl[nt], vd + 8192u);
            }
            #pragma unroll
            for (int j = 0; j < 8; j++) {
                const int bt = j >> 1, p = (j & 1) * 2;
                mma16816(of[j], pah[kk], vh[bt][p], vh[bt][p+1]);
                mma16816(of[j], pah[kk], vl[bt][p], vl[bt][p+1]);
                mma16816(of[j], pal[kk], vh[bt][p], vh[bt][p+1]);
            }
        }
        __syncthreads();
    }

    // ---- normalize, leaky_relu, split, store ----
    const float invA = 1.0f / lA, invB = 1.0f / lB;
    size_t obase = (size_t)(b*NT + q0 + wid*16 + g) * ND + h*64 + 2*t4;
    #pragma unroll
    for (int j = 0; j < 8; j++) {
        float o0 = of[j][0] * invA, o1 = of[j][1] * invA;
        float o2 = of[j][2] * invB, o3 = of[j][3] * invB;
        o0 = o0 >= 0.f ? o0 : 0.01f*o0;
        o1 = o1 >= 0.f ? o1 : 0.01f*o1;
        o2 = o2 >= 0.f ? o2 : 0.01f*o2;
        o3 = o3 >= 0.f ? o3 : 0.01f*o3;
        __nv_bfloat16 h0,h1,h2,h3,l0,l1,l2,l3;
        split2(o0,h0,l0); split2(o1,h1,l1); split2(o2,h2,l2); split2(o3,h3,l3);
        *reinterpret_cast<__nv_bfloat162*>(Oh + obase + j*8)            = __nv_bfloat162(h0,h1);
        *reinterpret_cast<__nv_bfloat162*>(Oh + obase + 8*ND + j*8)     = __nv_bfloat162(h2,h3);
        *reinterpret_cast<__nv_bfloat162*>(Ol + obase + j*8)            = __nv_bfloat162(l0,l1);
        *reinterpret_cast<__nv_bfloat162*>(Ol + obase + 8*ND + j*8)     = __nv_bfloat162(l2,l3);
    }
}

// ---------------- launch ----------------
#define GT_SMEM (132096)

extern "C" void kernel_launch(void* const* d_in, const int* in_sizes, int n_in,
                              void* d_out, int out_size) {
    const float* Z     = (const float*)d_in[0];
    const float* nmask = (const float*)d_in[1];
    const float* mask  = (const float*)d_in[2];
    const float* ln1g  = (const float*)d_in[3];
    const float* ln1b  = (const float*)d_in[4];
    const float* qkvw  = (const float*)d_in[5];
    const float* qkvb  = (const float*)d_in[6];
    const float* ow    = (const float*)d_in[7];
    const float* ln2g  = (const float*)d_in[8];
    const float* ln2b  = (const float*)d_in[9];
    const float* p1w   = (const float*)d_in[10];
    const float* p1b   = (const float*)d_in[11];
    const float* p2w   = (const float*)d_in[12];
    const float* p2b   = (const float*)d_in[13];
    float* out = (float*)d_out;

    __nv_bfloat16 *Znh,*Znl,*qkvh,*qkvl,*ah,*al,*Zn2h,*Zn2l,*hh,*hl;
    __nv_bfloat16 *wqh,*wql,*woh,*wol,*w1h,*w1l,*w2h,*w2l;
    float *Z1;
    cudaGetSymbolAddress((void**)&Znh,  g_Znh);  cudaGetSymbolAddress((void**)&Znl,  g_Znl);
    cudaGetSymbolAddress((void**)&qkvh, g_qkvh); cudaGetSymbolAddress((void**)&qkvl, g_qkvl);
    cudaGetSymbolAddress((void**)&ah,   g_ah);   cudaGetSymbolAddress((void**)&al,   g_al);
    cudaGetSymbolAddress((void**)&Z1,   g_Z1);
    cudaGetSymbolAddress((void**)&Zn2h, g_Zn2h); cudaGetSymbolAddress((void**)&Zn2l, g_Zn2l);
    cudaGetSymbolAddress((void**)&hh,   g_hh);   cudaGetSymbolAddress((void**)&hl,   g_hl);
    cudaGetSymbolAddress((void**)&wqh,  g_wqh);  cudaGetSymbolAddress((void**)&wql,  g_wql);
    cudaGetSymbolAddress((void**)&woh,  g_woh);  cudaGetSymbolAddress((void**)&wol,  g_wol);
    cudaGetSymbolAddress((void**)&w1h,  g_w1h);  cudaGetSymbolAddress((void**)&w1l,  g_w1l);
    cudaGetSymbolAddress((void**)&w2h,  g_w2h);  cudaGetSymbolAddress((void**)&w2l,  g_w2l);

    cudaFuncSetAttribute(gemm_tc, cudaFuncAttributeMaxDynamicSharedMemorySize, GT_SMEM);
    cudaFuncSetAttribute(attn_kernel, cudaFuncAttributeMaxDynamicSharedMemorySize, AT_SMEM);

    // merged weight splits (one launch)
    split4_kernel<<<(SP_N0+SP_N1+SP_N2+SP_N3 + 255)/256, 256>>>(
        qkvw, wqh, wql, ow, woh, wol, p1w, w1h, w1l, p2w, w2h, w2l);

    ln_kernel<<<NM, 256>>>(Z, ln1g, ln1b, Znh, Znl);
    gemm_tc<<<dim3(3*ND/128, NM/128), 256, GT_SMEM>>>(
        Znh, Znl, wqh, wql, qkvb, nullptr, nullptr, qkvh, qkvl, NM, 3*ND, ND, 2);
    attn_kernel<<<dim3(NH, NT/64, NB), 128, AT_SMEM>>>(qkvh, qkvl, nmask, mask, ah, al);
    gemm_tc<<<dim3(ND/128, NM/128), 256, GT_SMEM>>>(
        ah, al, woh, wol, nullptr, Z, Z1, nullptr, nullptr, NM, ND, ND, 0);
    ln_kernel<<<NM, 256>>>(Z1, ln2g, ln2b, Zn2h, Zn2l);
    gemm_tc<<<dim3(NDI/128, NM/128), 256, GT_SMEM>>>(
        Zn2h, Zn2l, w1h, w1l, p1b, nullptr, nullptr, hh, hl, NM, NDI, ND, 1);
    gemm_tc<<<dim3(ND/128, NM/128), 256, GT_SMEM>>>(
        hh, hl, w2h, w2l, p2b, Z1, out, nullptr, nullptr, NM, ND, NDI, 0);
}